// round 1
// baseline (speedup 1.0000x reference)
#include <cuda_runtime.h>

#define HID   1024
#define SEQ   2048
#define BATCH 2
#define NHEAD 16
#define HD    64
#define MTOT  (BATCH * SEQ)   /* 4096 */
#define FILLV (-10000.0f)

// Scratch (device globals; no runtime allocation allowed)
__device__ float g_qkv[(size_t)MTOT * 3 * HID];   // ~100.7 MB
__device__ float g_attn[(size_t)MTOT * HID];      // ~16.8 MB

// ---------------------------------------------------------------------------
// C[M,N] = A[M,K] @ W[K,N] + bias[N]
// Block tile 128x128, BK=8, 256 threads, 8x8 per-thread micro-tile.
// Requires M%128==0, N%128==0, K%8==0 (true for all our shapes).
// ---------------------------------------------------------------------------
__global__ __launch_bounds__(256) void gemm_bias_kernel(
    const float* __restrict__ A, const float* __restrict__ W,
    const float* __restrict__ bias, float* __restrict__ C,
    int M, int N, int K)
{
    __shared__ float As[8][128];
    __shared__ float Bs[8][128];

    const int t  = threadIdx.x;
    const int tx = t & 15;          // 0..15 (N dir)
    const int ty = t >> 4;          // 0..15 (M dir)
    const int n0 = blockIdx.x * 128;
    const int m0 = blockIdx.y * 128;

    float acc[8][8];
#pragma unroll
    for (int i = 0; i < 8; i++)
#pragma unroll
        for (int j = 0; j < 8; j++) acc[i][j] = 0.0f;

    const int a_row = t >> 1;           // 0..127
    const int a_kv  = (t & 1) * 4;      // 0 or 4
    const int b_kr  = t >> 5;           // 0..7
    const int b_nv  = (t & 31) * 4;     // 0..124

    for (int k0 = 0; k0 < K; k0 += 8) {
        // A tile: 128 rows x 8 k (store transposed)
        {
            float4 a4 = *reinterpret_cast<const float4*>(
                &A[(size_t)(m0 + a_row) * K + k0 + a_kv]);
            As[a_kv + 0][a_row] = a4.x;
            As[a_kv + 1][a_row] = a4.y;
            As[a_kv + 2][a_row] = a4.z;
            As[a_kv + 3][a_row] = a4.w;
        }
        // B tile: 8 k x 128 n
        {
            float4 b4 = *reinterpret_cast<const float4*>(
                &W[(size_t)(k0 + b_kr) * N + n0 + b_nv]);
            *reinterpret_cast<float4*>(&Bs[b_kr][b_nv]) = b4;
        }
        __syncthreads();

#pragma unroll
        for (int kk = 0; kk < 8; kk++) {
            float a[8], b[8];
#pragma unroll
            for (int i = 0; i < 8; i++) a[i] = As[kk][ty * 8 + i];
#pragma unroll
            for (int j = 0; j < 8; j++) b[j] = Bs[kk][tx * 8 + j];
#pragma unroll
            for (int i = 0; i < 8; i++)
#pragma unroll
                for (int j = 0; j < 8; j++)
                    acc[i][j] += a[i] * b[j];
        }
        __syncthreads();
    }

#pragma unroll
    for (int i = 0; i < 8; i++) {
        const size_t row = (size_t)(m0 + ty * 8 + i);
#pragma unroll
        for (int j = 0; j < 8; j++) {
            const int col = n0 + tx * 8 + j;
            C[row * N + col] = acc[i][j] + bias[col];
        }
    }
}

// ---------------------------------------------------------------------------
// Causal flash attention, fp32.
// grid = (SEQ/64, NHEAD, BATCH), 256 threads.
// Each CTA: 64 q rows for one (b,h). 4 threads per q-row; each thread owns
// 16 score columns and 16 output dims. K/V streamed in 64-row tiles.
// Shared (dynamic): Qs,Ks,Vs,Ss each 64x65 floats (padded) = 66,560 B.
// ---------------------------------------------------------------------------
__global__ __launch_bounds__(256) void attn_kernel(
    const float* __restrict__ qkv, float* __restrict__ out)
{
    extern __shared__ float smem[];
    float* Qs = smem;                // 64*65
    float* Ks = Qs + 64 * 65;
    float* Vs = Ks + 64 * 65;
    float* Ss = Vs + 64 * 65;

    const int t  = threadIdx.x;
    const int qt = blockIdx.x;       // q tile 0..31
    const int h  = blockIdx.y;
    const int b  = blockIdx.z;

    const int r  = t >> 2;           // q row within tile, 0..63
    const int cg = t & 3;            // quadrant
    const int c0 = cg * 16;          // score-col base
    const int d0 = cg * 16;          // out-dim base

    // Load Q tile (64 x 64)
    for (int i = t; i < 64 * 16; i += 256) {
        const int row = i >> 4;
        const int dv  = (i & 15) * 4;
        float4 v = *reinterpret_cast<const float4*>(
            &qkv[(size_t)(b * SEQ + qt * 64 + row) * (3 * HID) + h * HD + dv]);
        Qs[row * 65 + dv + 0] = v.x;
        Qs[row * 65 + dv + 1] = v.y;
        Qs[row * 65 + dv + 2] = v.z;
        Qs[row * 65 + dv + 3] = v.w;
    }

    float m = -1e30f, l = 0.0f;
    float acc[16];
#pragma unroll
    for (int j = 0; j < 16; j++) acc[j] = 0.0f;

    const int qglob = qt * 64 + r;

    for (int kt = 0; kt <= qt; kt++) {
        __syncthreads();  // protect Qs (iter 0) / Ks,Vs,Ss (iter>0) before overwrite

        // Load K and V tiles (64 x 64 each)
        for (int i = t; i < 64 * 16; i += 256) {
            const int row = i >> 4;
            const int dv  = (i & 15) * 4;
            const size_t base =
                (size_t)(b * SEQ + kt * 64 + row) * (3 * HID) + h * HD + dv;
            float4 k4 = *reinterpret_cast<const float4*>(&qkv[base + HID]);
            Ks[row * 65 + dv + 0] = k4.x;
            Ks[row * 65 + dv + 1] = k4.y;
            Ks[row * 65 + dv + 2] = k4.z;
            Ks[row * 65 + dv + 3] = k4.w;
            float4 v4 = *reinterpret_cast<const float4*>(&qkv[base + 2 * HID]);
            Vs[row * 65 + dv + 0] = v4.x;
            Vs[row * 65 + dv + 1] = v4.y;
            Vs[row * 65 + dv + 2] = v4.z;
            Vs[row * 65 + dv + 3] = v4.w;
        }
        __syncthreads();

        // Scores: s[j] = q[r] . k[c0+j]
        float s[16];
#pragma unroll
        for (int j = 0; j < 16; j++) s[j] = 0.0f;
        for (int kk = 0; kk < 64; kk++) {
            const float qv = Qs[r * 65 + kk];
#pragma unroll
            for (int j = 0; j < 16; j++)
                s[j] += qv * Ks[(c0 + j) * 65 + kk];
        }

        // Scale + causal mask (diagonal tile only) + row max
        float mx = -1e30f;
        const bool diag = (kt == qt);
#pragma unroll
        for (int j = 0; j < 16; j++) {
            s[j] *= 0.125f;  // 1/sqrt(64)
            if (diag && (kt * 64 + c0 + j) > qglob) s[j] = FILLV;
            mx = fmaxf(mx, s[j]);
        }
        mx = fmaxf(mx, __shfl_xor_sync(0xffffffffu, mx, 1));
        mx = fmaxf(mx, __shfl_xor_sync(0xffffffffu, mx, 2));

        const float mnew = fmaxf(m, mx);
        const float corr = __expf(m - mnew);

        float psum = 0.0f;
#pragma unroll
        for (int j = 0; j < 16; j++) {
            const float p = __expf(s[j] - mnew);
            Ss[r * 65 + c0 + j] = p;
            psum += p;
        }
        psum += __shfl_xor_sync(0xffffffffu, psum, 1);
        psum += __shfl_xor_sync(0xffffffffu, psum, 2);

        l = l * corr + psum;
        m = mnew;
#pragma unroll
        for (int j = 0; j < 16; j++) acc[j] *= corr;

        __syncthreads();  // Ss visible to all 4 quadrants of each row

        // acc += P . V
        for (int c = 0; c < 64; c++) {
            const float p = Ss[r * 65 + c];
#pragma unroll
            for (int j = 0; j < 16; j++)
                acc[j] += p * Vs[c * 65 + d0 + j];
        }
    }

    const float inv = 1.0f / l;
    const size_t orow = (size_t)(b * SEQ + qglob) * HID + h * HD + d0;
#pragma unroll
    for (int j = 0; j < 16; j++) out[orow + j] = acc[j] * inv;
}

// ---------------------------------------------------------------------------
extern "C" void kernel_launch(void* const* d_in, const int* in_sizes, int n_in,
                              void* d_out, int out_size)
{
    const float* x     = (const float*)d_in[0];
    const float* W_qkv = (const float*)d_in[1];
    const float* b_qkv = (const float*)d_in[2];
    const float* W_o   = (const float*)d_in[3];
    const float* b_o   = (const float*)d_in[4];
    float* out = (float*)d_out;

    float* qkv;
    float* attn;
    cudaGetSymbolAddress((void**)&qkv, g_qkv);
    cudaGetSymbolAddress((void**)&attn, g_attn);

    const int smem_attn = 4 * 64 * 65 * (int)sizeof(float);  // 66,560 B
    cudaFuncSetAttribute(attn_kernel,
                         cudaFuncAttributeMaxDynamicSharedMemorySize, smem_attn);

    // 1) QKV projection: [4096,1024] @ [1024,3072] + bias
    gemm_bias_kernel<<<dim3(3 * HID / 128, MTOT / 128), 256>>>(
        x, W_qkv, b_qkv, qkv, MTOT, 3 * HID, HID);

    // 2) Causal attention per (b, h)
    attn_kernel<<<dim3(SEQ / 64, NHEAD, BATCH), 256, smem_attn>>>(qkv, attn);

    // 3) Output projection: [4096,1024] @ [1024,1024] + bias
    gemm_bias_kernel<<<dim3(HID / 128, MTOT / 128), 256>>>(
        attn, W_o, b_o, out, MTOT, HID, HID);
}

// round 2
// speedup vs baseline: 3.1747x; 3.1747x over previous
#include <cuda_runtime.h>
#include <cstdint>

#define HID   1024
#define SEQ   2048
#define BATCH 2
#define NHEAD 16
#define HD    64
#define MTOT  (BATCH * SEQ)   /* 4096 */
#define FILLV (-10000.0f)

#define PADQ 68   /* pad for Qs/Ks/Ss rows: (4g+tg) conflict-free fragment LDS */
#define PADV 72   /* pad for Vs rows: (8tg+g) conflict-free fragment LDS */

// Scratch (device globals; no runtime allocation allowed)
__device__ float g_qkv[(size_t)MTOT * 3 * HID];   // ~100.7 MB
__device__ float g_attn[(size_t)MTOT * HID];      // ~16.8 MB

// ---------------------------------------------------------------------------
// C[M,N] = A[M,K] @ W[K,N] + bias[N]   (fp32 FFMA, unchanged from R0)
// ---------------------------------------------------------------------------
__global__ __launch_bounds__(256) void gemm_bias_kernel(
    const float* __restrict__ A, const float* __restrict__ W,
    const float* __restrict__ bias, float* __restrict__ C,
    int M, int N, int K)
{
    __shared__ float As[8][128];
    __shared__ float Bs[8][128];

    const int t  = threadIdx.x;
    const int tx = t & 15;
    const int ty = t >> 4;
    const int n0 = blockIdx.x * 128;
    const int m0 = blockIdx.y * 128;

    float acc[8][8];
#pragma unroll
    for (int i = 0; i < 8; i++)
#pragma unroll
        for (int j = 0; j < 8; j++) acc[i][j] = 0.0f;

    const int a_row = t >> 1;
    const int a_kv  = (t & 1) * 4;
    const int b_kr  = t >> 5;
    const int b_nv  = (t & 31) * 4;

    for (int k0 = 0; k0 < K; k0 += 8) {
        {
            float4 a4 = *reinterpret_cast<const float4*>(
                &A[(size_t)(m0 + a_row) * K + k0 + a_kv]);
            As[a_kv + 0][a_row] = a4.x;
            As[a_kv + 1][a_row] = a4.y;
            As[a_kv + 2][a_row] = a4.z;
            As[a_kv + 3][a_row] = a4.w;
        }
        {
            float4 b4 = *reinterpret_cast<const float4*>(
                &W[(size_t)(k0 + b_kr) * N + n0 + b_nv]);
            *reinterpret_cast<float4*>(&Bs[b_kr][b_nv]) = b4;
        }
        __syncthreads();

#pragma unroll
        for (int kk = 0; kk < 8; kk++) {
            float a[8], b[8];
#pragma unroll
            for (int i = 0; i < 8; i++) a[i] = As[kk][ty * 8 + i];
#pragma unroll
            for (int j = 0; j < 8; j++) b[j] = Bs[kk][tx * 8 + j];
#pragma unroll
            for (int i = 0; i < 8; i++)
#pragma unroll
                for (int j = 0; j < 8; j++)
                    acc[i][j] += a[i] * b[j];
        }
        __syncthreads();
    }

#pragma unroll
    for (int i = 0; i < 8; i++) {
        const size_t row = (size_t)(m0 + ty * 8 + i);
#pragma unroll
        for (int j = 0; j < 8; j++) {
            const int col = n0 + tx * 8 + j;
            C[row * N + col] = acc[i][j] + bias[col];
        }
    }
}

// ---------------------------------------------------------------------------
// tf32 helpers
// ---------------------------------------------------------------------------
__device__ __forceinline__ uint32_t f2tf(float x) {
    uint32_t r;
    asm("cvt.rna.tf32.f32 %0, %1;" : "=r"(r) : "f"(x));
    return r;
}

__device__ __forceinline__ void mma_tf32(float c[4],
    uint32_t a0, uint32_t a1, uint32_t a2, uint32_t a3,
    uint32_t b0, uint32_t b1)
{
    asm volatile(
        "mma.sync.aligned.m16n8k8.row.col.f32.tf32.tf32.f32 "
        "{%0,%1,%2,%3}, {%4,%5,%6,%7}, {%8,%9}, {%0,%1,%2,%3};\n"
        : "+f"(c[0]), "+f"(c[1]), "+f"(c[2]), "+f"(c[3])
        : "r"(a0), "r"(a1), "r"(a2), "r"(a3), "r"(b0), "r"(b1));
}

// ---------------------------------------------------------------------------
// Causal flash attention with m16n8k8 tf32 MMA.
// grid = (SEQ/64, NHEAD, BATCH), 128 threads = 4 warps.
// Each warp: 16 q rows. Fragments per PTX m16n8k8 tf32 layout:
//   A: a0=(g,tg) a1=(g+8,tg) a2=(g,tg+4) a3=(g+8,tg+4)
//   B: b0=(k=tg,n=g) b1=(k=tg+4,n=g)
//   C: c0=(g,2tg) c1=(g,2tg+1) c2=(g+8,2tg) c3=(g+8,2tg+1)
// ---------------------------------------------------------------------------
__global__ __launch_bounds__(128) void attn_mma_kernel(
    const float* __restrict__ qkv, float* __restrict__ out)
{
    extern __shared__ float smem[];
    float* Qs = smem;                 // 64*PADQ
    float* Ks = Qs + 64 * PADQ;       // 64*PADQ
    float* Ss = Ks + 64 * PADQ;       // 64*PADQ
    float* Vs = Ss + 64 * PADQ;       // 64*PADV

    const int t    = threadIdx.x;
    const int warp = t >> 5;
    const int lane = t & 31;
    const int g    = lane >> 2;       // groupID 0..7
    const int tg   = lane & 3;        // thread-in-group 0..3

    const int qt = gridDim.x - 1 - blockIdx.x;  // heavy tiles first
    const int h  = blockIdx.y;
    const int b  = blockIdx.z;
    const int q0w = warp * 16;

    // Load Q tile (64x64), tf32-rounded
    for (int i = t; i < 64 * 16; i += 128) {
        const int row = i >> 4;
        const int dv  = (i & 15) * 4;
        float4 v = *reinterpret_cast<const float4*>(
            &qkv[(size_t)(b * SEQ + qt * 64 + row) * (3 * HID) + h * HD + dv]);
        float4 w;
        w.x = __uint_as_float(f2tf(v.x));
        w.y = __uint_as_float(f2tf(v.y));
        w.z = __uint_as_float(f2tf(v.z));
        w.w = __uint_as_float(f2tf(v.w));
        *reinterpret_cast<float4*>(&Qs[row * PADQ + dv]) = w;
    }

    float mrow0 = -1e30f, mrow1 = -1e30f;
    float lrow0 = 0.0f,   lrow1 = 0.0f;
    float o[8][4];
#pragma unroll
    for (int nt = 0; nt < 8; nt++)
#pragma unroll
        for (int e = 0; e < 4; e++) o[nt][e] = 0.0f;

    const int r0 = qt * 64 + q0w + g;   // global q row (low)
    const int r1 = r0 + 8;              // global q row (high)

    for (int kt = 0; kt <= qt; kt++) {
        __syncthreads();  // Q ready (iter 0) / K,V consumed (iter>0)

        // Load K and V tiles, tf32-rounded
        for (int i = t; i < 64 * 16; i += 128) {
            const int row = i >> 4;
            const int dv  = (i & 15) * 4;
            const size_t base =
                (size_t)(b * SEQ + kt * 64 + row) * (3 * HID) + h * HD + dv;
            float4 k4 = *reinterpret_cast<const float4*>(&qkv[base + HID]);
            float4 kw;
            kw.x = __uint_as_float(f2tf(k4.x));
            kw.y = __uint_as_float(f2tf(k4.y));
            kw.z = __uint_as_float(f2tf(k4.z));
            kw.w = __uint_as_float(f2tf(k4.w));
            *reinterpret_cast<float4*>(&Ks[row * PADQ + dv]) = kw;
            float4 v4 = *reinterpret_cast<const float4*>(&qkv[base + 2 * HID]);
            float4 vw;
            vw.x = __uint_as_float(f2tf(v4.x));
            vw.y = __uint_as_float(f2tf(v4.y));
            vw.z = __uint_as_float(f2tf(v4.z));
            vw.w = __uint_as_float(f2tf(v4.w));
            *reinterpret_cast<float4*>(&Vs[row * PADV + dv]) = vw;
        }
        __syncthreads();

        // ---- Scores: warp's 16 x 64 tile = 8 n-tiles, k=64 in 8 steps ----
        float sc[8][4];
#pragma unroll
        for (int nt = 0; nt < 8; nt++)
#pragma unroll
            for (int e = 0; e < 4; e++) sc[nt][e] = 0.0f;

#pragma unroll
        for (int k8 = 0; k8 < 64; k8 += 8) {
            const uint32_t a0 = __float_as_uint(Qs[(q0w + g)     * PADQ + k8 + tg]);
            const uint32_t a1 = __float_as_uint(Qs[(q0w + g + 8) * PADQ + k8 + tg]);
            const uint32_t a2 = __float_as_uint(Qs[(q0w + g)     * PADQ + k8 + tg + 4]);
            const uint32_t a3 = __float_as_uint(Qs[(q0w + g + 8) * PADQ + k8 + tg + 4]);
#pragma unroll
            for (int nt = 0; nt < 8; nt++) {
                const uint32_t b0 = __float_as_uint(Ks[(nt * 8 + g) * PADQ + k8 + tg]);
                const uint32_t b1 = __float_as_uint(Ks[(nt * 8 + g) * PADQ + k8 + tg + 4]);
                mma_tf32(sc[nt], a0, a1, a2, a3, b0, b1);
            }
        }

        // ---- Scale + causal mask + online softmax ----
        const bool diag = (kt == qt);
        float mx0 = -1e30f, mx1 = -1e30f;
#pragma unroll
        for (int nt = 0; nt < 8; nt++) {
            const int c = kt * 64 + nt * 8 + tg * 2;
#pragma unroll
            for (int e = 0; e < 4; e++) sc[nt][e] *= 0.125f;
            if (diag) {
                if (c     > r0) sc[nt][0] = FILLV;
                if (c + 1 > r0) sc[nt][1] = FILLV;
                if (c     > r1) sc[nt][2] = FILLV;
                if (c + 1 > r1) sc[nt][3] = FILLV;
            }
            mx0 = fmaxf(mx0, fmaxf(sc[nt][0], sc[nt][1]));
            mx1 = fmaxf(mx1, fmaxf(sc[nt][2], sc[nt][3]));
        }
        mx0 = fmaxf(mx0, __shfl_xor_sync(0xffffffffu, mx0, 1));
        mx0 = fmaxf(mx0, __shfl_xor_sync(0xffffffffu, mx0, 2));
        mx1 = fmaxf(mx1, __shfl_xor_sync(0xffffffffu, mx1, 1));
        mx1 = fmaxf(mx1, __shfl_xor_sync(0xffffffffu, mx1, 2));

        const float mn0 = fmaxf(mrow0, mx0);
        const float mn1 = fmaxf(mrow1, mx1);
        const float corr0 = __expf(mrow0 - mn0);
        const float corr1 = __expf(mrow1 - mn1);

        float ps0 = 0.0f, ps1 = 0.0f;
#pragma unroll
        for (int nt = 0; nt < 8; nt++) {
            const float p0 = __expf(sc[nt][0] - mn0);
            const float p1 = __expf(sc[nt][1] - mn0);
            const float p2 = __expf(sc[nt][2] - mn1);
            const float p3 = __expf(sc[nt][3] - mn1);
            ps0 += p0 + p1;
            ps1 += p2 + p3;
            *reinterpret_cast<float2*>(&Ss[(q0w + g)     * PADQ + nt * 8 + tg * 2]) =
                make_float2(__uint_as_float(f2tf(p0)), __uint_as_float(f2tf(p1)));
            *reinterpret_cast<float2*>(&Ss[(q0w + g + 8) * PADQ + nt * 8 + tg * 2]) =
                make_float2(__uint_as_float(f2tf(p2)), __uint_as_float(f2tf(p3)));
        }
        ps0 += __shfl_xor_sync(0xffffffffu, ps0, 1);
        ps0 += __shfl_xor_sync(0xffffffffu, ps0, 2);
        ps1 += __shfl_xor_sync(0xffffffffu, ps1, 1);
        ps1 += __shfl_xor_sync(0xffffffffu, ps1, 2);

        lrow0 = lrow0 * corr0 + ps0;
        lrow1 = lrow1 * corr1 + ps1;
        mrow0 = mn0;
        mrow1 = mn1;
#pragma unroll
        for (int nt = 0; nt < 8; nt++) {
            o[nt][0] *= corr0; o[nt][1] *= corr0;
            o[nt][2] *= corr1; o[nt][3] *= corr1;
        }

        __syncwarp();  // Ss rows are warp-private: warp-level visibility only

        // ---- P @ V : k = key dim (64, 8 steps), n = head dim (8 n-tiles) ----
#pragma unroll
        for (int k8 = 0; k8 < 64; k8 += 8) {
            const uint32_t a0 = __float_as_uint(Ss[(q0w + g)     * PADQ + k8 + tg]);
            const uint32_t a1 = __float_as_uint(Ss[(q0w + g + 8) * PADQ + k8 + tg]);
            const uint32_t a2 = __float_as_uint(Ss[(q0w + g)     * PADQ + k8 + tg + 4]);
            const uint32_t a3 = __float_as_uint(Ss[(q0w + g + 8) * PADQ + k8 + tg + 4]);
#pragma unroll
            for (int nt = 0; nt < 8; nt++) {
                const uint32_t b0 = __float_as_uint(Vs[(k8 + tg)     * PADV + nt * 8 + g]);
                const uint32_t b1 = __float_as_uint(Vs[(k8 + tg + 4) * PADV + nt * 8 + g]);
                mma_tf32(o[nt], a0, a1, a2, a3, b0, b1);
            }
        }
        __syncwarp();  // Ss reads done before next iteration's stores
    }

    const float i0 = 1.0f / lrow0;
    const float i1 = 1.0f / lrow1;
    const size_t base0 = (size_t)(b * SEQ + r0) * HID + h * HD;
    const size_t base1 = base0 + (size_t)8 * HID;
#pragma unroll
    for (int nt = 0; nt < 8; nt++) {
        *reinterpret_cast<float2*>(&out[base0 + nt * 8 + tg * 2]) =
            make_float2(o[nt][0] * i0, o[nt][1] * i0);
        *reinterpret_cast<float2*>(&out[base1 + nt * 8 + tg * 2]) =
            make_float2(o[nt][2] * i1, o[nt][3] * i1);
    }
}

// ---------------------------------------------------------------------------
extern "C" void kernel_launch(void* const* d_in, const int* in_sizes, int n_in,
                              void* d_out, int out_size)
{
    const float* x     = (const float*)d_in[0];
    const float* W_qkv = (const float*)d_in[1];
    const float* b_qkv = (const float*)d_in[2];
    const float* W_o   = (const float*)d_in[3];
    const float* b_o   = (const float*)d_in[4];
    float* out = (float*)d_out;

    float* qkv;
    float* attn;
    cudaGetSymbolAddress((void**)&qkv, g_qkv);
    cudaGetSymbolAddress((void**)&attn, g_attn);

    const int smem_attn = (3 * 64 * PADQ + 64 * PADV) * (int)sizeof(float); // 70656
    cudaFuncSetAttribute(attn_mma_kernel,
                         cudaFuncAttributeMaxDynamicSharedMemorySize, smem_attn);

    // 1) QKV projection: [4096,1024] @ [1024,3072] + bias
    gemm_bias_kernel<<<dim3(3 * HID / 128, MTOT / 128), 256>>>(
        x, W_qkv, b_qkv, qkv, MTOT, 3 * HID, HID);

    // 2) Causal attention per (b, h) — tf32 MMA
    attn_mma_kernel<<<dim3(SEQ / 64, NHEAD, BATCH), 128, smem_attn>>>(qkv, attn);

    // 3) Output projection: [4096,1024] @ [1024,1024] + bias
    gemm_bias_kernel<<<dim3(HID / 128, MTOT / 128), 256>>>(
        attn, W_o, b_o, out, MTOT, HID, HID);
}

// round 3
// speedup vs baseline: 5.3405x; 1.6822x over previous
#include <cuda_runtime.h>
#include <cstdint>

#define HID   1024
#define SEQ   2048
#define BATCH 2
#define NHEAD 16
#define HD    64
#define MTOT  (BATCH * SEQ)   /* 4096 */
#define FILLV (-10000.0f)

#define PADQ 68   /* attention: Qs/Ks/Ss row pad */
#define PADV 72   /* attention: Vs row pad */

#define PA 36     /* gemm: A smem row pad (words): frag bank = 4g+tg */
#define PB 132    /* gemm: B smem row pad (words): frag bank = 4tg+g */

// Scratch (device globals; no runtime allocation allowed)
__device__ float g_qkv[(size_t)MTOT * 3 * HID];   // ~100.7 MB
__device__ float g_attn[(size_t)MTOT * HID];      // ~16.8 MB

// ---------------------------------------------------------------------------
// tf32 helpers
// ---------------------------------------------------------------------------
__device__ __forceinline__ uint32_t f2tf(float x) {
    uint32_t r;
    asm("cvt.rna.tf32.f32 %0, %1;" : "=r"(r) : "f"(x));
    return r;
}
__device__ __forceinline__ float f2tff(float x) {
    return __uint_as_float(f2tf(x));
}

__device__ __forceinline__ void mma_tf32(float c[4],
    uint32_t a0, uint32_t a1, uint32_t a2, uint32_t a3,
    uint32_t b0, uint32_t b1)
{
    asm volatile(
        "mma.sync.aligned.m16n8k8.row.col.f32.tf32.tf32.f32 "
        "{%0,%1,%2,%3}, {%4,%5,%6,%7}, {%8,%9}, {%0,%1,%2,%3};\n"
        : "+f"(c[0]), "+f"(c[1]), "+f"(c[2]), "+f"(c[3])
        : "r"(a0), "r"(a1), "r"(a2), "r"(a3), "r"(b0), "r"(b1));
}

// ---------------------------------------------------------------------------
// C[M,N] = A[M,K] @ W[K,N] + bias[N]   -- tf32 tensor-core GEMM
// Block 128x128, BK=32, 256 threads (8 warps, warp tile 32x64).
// Single smem buffer + register prefetch of the next K-slice.
// Requires M%128==0, N%128==0, K%32==0.
// ---------------------------------------------------------------------------
__global__ __launch_bounds__(256, 2) void gemm_mma_kernel(
    const float* __restrict__ A, const float* __restrict__ W,
    const float* __restrict__ bias, float* __restrict__ C,
    int M, int N, int K)
{
    __shared__ float As[128 * PA];   // [row][k] row-major, pad 36
    __shared__ float Bs[32 * PB];    // [k][n]  row-major, pad 132

    const int t    = threadIdx.x;
    const int warp = t >> 5;
    const int lane = t & 31;
    const int g    = lane >> 2;
    const int tg   = lane & 3;
    const int wm   = (warp & 3) * 32;     // warp m-offset (4 warps in m)
    const int wn   = (warp >> 2) * 64;    // warp n-offset (2 warps in n)
    const int m0   = blockIdx.y * 128;
    const int n0   = blockIdx.x * 128;

    // global-load mapping
    const int ar = t >> 1;            // A row 0..127
    const int ak = (t & 1) * 16;      // A k-half 0/16
    const int br = t >> 3;            // B k-row 0..31
    const int bn = (t & 7) * 16;      // B n base 0..112

    float4 pa[4], pb[4];

    // prologue: tile 0 -> smem
#pragma unroll
    for (int j = 0; j < 4; j++)
        pa[j] = *reinterpret_cast<const float4*>(
            &A[(size_t)(m0 + ar) * K + ak + j * 4]);
#pragma unroll
    for (int j = 0; j < 4; j++)
        pb[j] = *reinterpret_cast<const float4*>(
            &W[(size_t)br * N + n0 + bn + j * 4]);
#pragma unroll
    for (int j = 0; j < 4; j++) {
        float4 va = pa[j];
        va.x = f2tff(va.x); va.y = f2tff(va.y);
        va.z = f2tff(va.z); va.w = f2tff(va.w);
        *reinterpret_cast<float4*>(&As[ar * PA + ak + j * 4]) = va;
        float4 vb = pb[j];
        vb.x = f2tff(vb.x); vb.y = f2tff(vb.y);
        vb.z = f2tff(vb.z); vb.w = f2tff(vb.w);
        *reinterpret_cast<float4*>(&Bs[br * PB + bn + j * 4]) = vb;
    }
    __syncthreads();

    float c[2][8][4];
#pragma unroll
    for (int mi = 0; mi < 2; mi++)
#pragma unroll
        for (int nt = 0; nt < 8; nt++)
#pragma unroll
            for (int e = 0; e < 4; e++) c[mi][nt][e] = 0.0f;

    const int iters = K / 32;
    for (int it = 0; it < iters; it++) {
        // prefetch next K-slice into registers (latency hidden by MMAs)
        if (it + 1 < iters) {
            const int k0 = (it + 1) * 32;
#pragma unroll
            for (int j = 0; j < 4; j++)
                pa[j] = *reinterpret_cast<const float4*>(
                    &A[(size_t)(m0 + ar) * K + k0 + ak + j * 4]);
#pragma unroll
            for (int j = 0; j < 4; j++)
                pb[j] = *reinterpret_cast<const float4*>(
                    &W[(size_t)(k0 + br) * N + n0 + bn + j * 4]);
        }

        // compute on current smem tile: 4 k8-steps x (2 mi x 8 nt) MMAs
#pragma unroll
        for (int k8 = 0; k8 < 32; k8 += 8) {
            uint32_t a0[2], a1[2], a2[2], a3[2];
#pragma unroll
            for (int mi = 0; mi < 2; mi++) {
                const int row = wm + mi * 16;
                a0[mi] = __float_as_uint(As[(row + g)     * PA + k8 + tg]);
                a1[mi] = __float_as_uint(As[(row + g + 8) * PA + k8 + tg]);
                a2[mi] = __float_as_uint(As[(row + g)     * PA + k8 + tg + 4]);
                a3[mi] = __float_as_uint(As[(row + g + 8) * PA + k8 + tg + 4]);
            }
#pragma unroll
            for (int nt = 0; nt < 8; nt++) {
                const uint32_t b0 =
                    __float_as_uint(Bs[(k8 + tg)     * PB + wn + nt * 8 + g]);
                const uint32_t b1 =
                    __float_as_uint(Bs[(k8 + tg + 4) * PB + wn + nt * 8 + g]);
                mma_tf32(c[0][nt], a0[0], a1[0], a2[0], a3[0], b0, b1);
                mma_tf32(c[1][nt], a0[1], a1[1], a2[1], a3[1], b0, b1);
            }
        }
        __syncthreads();   // everyone done reading smem

        if (it + 1 < iters) {
#pragma unroll
            for (int j = 0; j < 4; j++) {
                float4 va = pa[j];
                va.x = f2tff(va.x); va.y = f2tff(va.y);
                va.z = f2tff(va.z); va.w = f2tff(va.w);
                *reinterpret_cast<float4*>(&As[ar * PA + ak + j * 4]) = va;
                float4 vb = pb[j];
                vb.x = f2tff(vb.x); vb.y = f2tff(vb.y);
                vb.z = f2tff(vb.z); vb.w = f2tff(vb.w);
                *reinterpret_cast<float4*>(&Bs[br * PB + bn + j * 4]) = vb;
            }
        }
        __syncthreads();   // new tile visible
    }

    // epilogue: bias + store (C frag: c0=(g,2tg) c1=(g,2tg+1) c2/c3 = +8 rows)
#pragma unroll
    for (int mi = 0; mi < 2; mi++) {
#pragma unroll
        for (int nt = 0; nt < 8; nt++) {
            const int row = m0 + wm + mi * 16 + g;
            const int col = n0 + wn + nt * 8 + tg * 2;
            const float bv0 = bias[col];
            const float bv1 = bias[col + 1];
            *reinterpret_cast<float2*>(&C[(size_t)row * N + col]) =
                make_float2(c[mi][nt][0] + bv0, c[mi][nt][1] + bv1);
            *reinterpret_cast<float2*>(&C[(size_t)(row + 8) * N + col]) =
                make_float2(c[mi][nt][2] + bv0, c[mi][nt][3] + bv1);
        }
    }
}

// ---------------------------------------------------------------------------
// Causal flash attention with m16n8k8 tf32 MMA (unchanged from R1).
// grid = (SEQ/64, NHEAD, BATCH), 128 threads = 4 warps.
// ---------------------------------------------------------------------------
__global__ __launch_bounds__(128) void attn_mma_kernel(
    const float* __restrict__ qkv, float* __restrict__ out)
{
    extern __shared__ float smem[];
    float* Qs = smem;                 // 64*PADQ
    float* Ks = Qs + 64 * PADQ;       // 64*PADQ
    float* Ss = Ks + 64 * PADQ;       // 64*PADQ
    float* Vs = Ss + 64 * PADQ;       // 64*PADV

    const int t    = threadIdx.x;
    const int warp = t >> 5;
    const int lane = t & 31;
    const int g    = lane >> 2;
    const int tg   = lane & 3;

    const int qt = gridDim.x - 1 - blockIdx.x;  // heavy tiles first
    const int h  = blockIdx.y;
    const int b  = blockIdx.z;
    const int q0w = warp * 16;

    for (int i = t; i < 64 * 16; i += 128) {
        const int row = i >> 4;
        const int dv  = (i & 15) * 4;
        float4 v = *reinterpret_cast<const float4*>(
            &qkv[(size_t)(b * SEQ + qt * 64 + row) * (3 * HID) + h * HD + dv]);
        float4 w;
        w.x = f2tff(v.x); w.y = f2tff(v.y);
        w.z = f2tff(v.z); w.w = f2tff(v.w);
        *reinterpret_cast<float4*>(&Qs[row * PADQ + dv]) = w;
    }

    float mrow0 = -1e30f, mrow1 = -1e30f;
    float lrow0 = 0.0f,   lrow1 = 0.0f;
    float o[8][4];
#pragma unroll
    for (int nt = 0; nt < 8; nt++)
#pragma unroll
        for (int e = 0; e < 4; e++) o[nt][e] = 0.0f;

    const int r0 = qt * 64 + q0w + g;
    const int r1 = r0 + 8;

    for (int kt = 0; kt <= qt; kt++) {
        __syncthreads();

        for (int i = t; i < 64 * 16; i += 128) {
            const int row = i >> 4;
            const int dv  = (i & 15) * 4;
            const size_t base =
                (size_t)(b * SEQ + kt * 64 + row) * (3 * HID) + h * HD + dv;
            float4 k4 = *reinterpret_cast<const float4*>(&qkv[base + HID]);
            float4 kw;
            kw.x = f2tff(k4.x); kw.y = f2tff(k4.y);
            kw.z = f2tff(k4.z); kw.w = f2tff(k4.w);
            *reinterpret_cast<float4*>(&Ks[row * PADQ + dv]) = kw;
            float4 v4 = *reinterpret_cast<const float4*>(&qkv[base + 2 * HID]);
            float4 vw;
            vw.x = f2tff(v4.x); vw.y = f2tff(v4.y);
            vw.z = f2tff(v4.z); vw.w = f2tff(v4.w);
            *reinterpret_cast<float4*>(&Vs[row * PADV + dv]) = vw;
        }
        __syncthreads();

        float sc[8][4];
#pragma unroll
        for (int nt = 0; nt < 8; nt++)
#pragma unroll
            for (int e = 0; e < 4; e++) sc[nt][e] = 0.0f;

#pragma unroll
        for (int k8 = 0; k8 < 64; k8 += 8) {
            const uint32_t a0 = __float_as_uint(Qs[(q0w + g)     * PADQ + k8 + tg]);
            const uint32_t a1 = __float_as_uint(Qs[(q0w + g + 8) * PADQ + k8 + tg]);
            const uint32_t a2 = __float_as_uint(Qs[(q0w + g)     * PADQ + k8 + tg + 4]);
            const uint32_t a3 = __float_as_uint(Qs[(q0w + g + 8) * PADQ + k8 + tg + 4]);
#pragma unroll
            for (int nt = 0; nt < 8; nt++) {
                const uint32_t b0 = __float_as_uint(Ks[(nt * 8 + g) * PADQ + k8 + tg]);
                const uint32_t b1 = __float_as_uint(Ks[(nt * 8 + g) * PADQ + k8 + tg + 4]);
                mma_tf32(sc[nt], a0, a1, a2, a3, b0, b1);
            }
        }

        const bool diag = (kt == qt);
        float mx0 = -1e30f, mx1 = -1e30f;
#pragma unroll
        for (int nt = 0; nt < 8; nt++) {
            const int cc = kt * 64 + nt * 8 + tg * 2;
#pragma unroll
            for (int e = 0; e < 4; e++) sc[nt][e] *= 0.125f;
            if (diag) {
                if (cc     > r0) sc[nt][0] = FILLV;
                if (cc + 1 > r0) sc[nt][1] = FILLV;
                if (cc     > r1) sc[nt][2] = FILLV;
                if (cc + 1 > r1) sc[nt][3] = FILLV;
            }
            mx0 = fmaxf(mx0, fmaxf(sc[nt][0], sc[nt][1]));
            mx1 = fmaxf(mx1, fmaxf(sc[nt][2], sc[nt][3]));
        }
        mx0 = fmaxf(mx0, __shfl_xor_sync(0xffffffffu, mx0, 1));
        mx0 = fmaxf(mx0, __shfl_xor_sync(0xffffffffu, mx0, 2));
        mx1 = fmaxf(mx1, __shfl_xor_sync(0xffffffffu, mx1, 1));
        mx1 = fmaxf(mx1, __shfl_xor_sync(0xffffffffu, mx1, 2));

        const float mn0 = fmaxf(mrow0, mx0);
        const float mn1 = fmaxf(mrow1, mx1);
        const float corr0 = __expf(mrow0 - mn0);
        const float corr1 = __expf(mrow1 - mn1);

        float ps0 = 0.0f, ps1 = 0.0f;
#pragma unroll
        for (int nt = 0; nt < 8; nt++) {
            const float p0 = __expf(sc[nt][0] - mn0);
            const float p1 = __expf(sc[nt][1] - mn0);
            const float p2 = __expf(sc[nt][2] - mn1);
            const float p3 = __expf(sc[nt][3] - mn1);
            ps0 += p0 + p1;
            ps1 += p2 + p3;
            *reinterpret_cast<float2*>(&Ss[(q0w + g)     * PADQ + nt * 8 + tg * 2]) =
                make_float2(f2tff(p0), f2tff(p1));
            *reinterpret_cast<float2*>(&Ss[(q0w + g + 8) * PADQ + nt * 8 + tg * 2]) =
                make_float2(f2tff(p2), f2tff(p3));
        }
        ps0 += __shfl_xor_sync(0xffffffffu, ps0, 1);
        ps0 += __shfl_xor_sync(0xffffffffu, ps0, 2);
        ps1 += __shfl_xor_sync(0xffffffffu, ps1, 1);
        ps1 += __shfl_xor_sync(0xffffffffu, ps1, 2);

        lrow0 = lrow0 * corr0 + ps0;
        lrow1 = lrow1 * corr1 + ps1;
        mrow0 = mn0;
        mrow1 = mn1;
#pragma unroll
        for (int nt = 0; nt < 8; nt++) {
            o[nt][0] *= corr0; o[nt][1] *= corr0;
            o[nt][2] *= corr1; o[nt][3] *= corr1;
        }

        __syncwarp();

#pragma unroll
        for (int k8 = 0; k8 < 64; k8 += 8) {
            const uint32_t a0 = __float_as_uint(Ss[(q0w + g)     * PADQ + k8 + tg]);
            const uint32_t a1 = __float_as_uint(Ss[(q0w + g + 8) * PADQ + k8 + tg]);
            const uint32_t a2 = __float_as_uint(Ss[(q0w + g)     * PADQ + k8 + tg + 4]);
            const uint32_t a3 = __float_as_uint(Ss[(q0w + g + 8) * PADQ + k8 + tg + 4]);
#pragma unroll
            for (int nt = 0; nt < 8; nt++) {
                const uint32_t b0 = __float_as_uint(Vs[(k8 + tg)     * PADV + nt * 8 + g]);
                const uint32_t b1 = __float_as_uint(Vs[(k8 + tg + 4) * PADV + nt * 8 + g]);
                mma_tf32(o[nt], a0, a1, a2, a3, b0, b1);
            }
        }
        __syncwarp();
    }

    const float i0 = 1.0f / lrow0;
    const float i1 = 1.0f / lrow1;
    const size_t base0 = (size_t)(b * SEQ + r0) * HID + h * HD;
    const size_t base1 = base0 + (size_t)8 * HID;
#pragma unroll
    for (int nt = 0; nt < 8; nt++) {
        *reinterpret_cast<float2*>(&out[base0 + nt * 8 + tg * 2]) =
            make_float2(o[nt][0] * i0, o[nt][1] * i0);
        *reinterpret_cast<float2*>(&out[base1 + nt * 8 + tg * 2]) =
            make_float2(o[nt][2] * i1, o[nt][3] * i1);
    }
}

// ---------------------------------------------------------------------------
extern "C" void kernel_launch(void* const* d_in, const int* in_sizes, int n_in,
                              void* d_out, int out_size)
{
    const float* x     = (const float*)d_in[0];
    const float* W_qkv = (const float*)d_in[1];
    const float* b_qkv = (const float*)d_in[2];
    const float* W_o   = (const float*)d_in[3];
    const float* b_o   = (const float*)d_in[4];
    float* out = (float*)d_out;

    float* qkv;
    float* attn;
    cudaGetSymbolAddress((void**)&qkv, g_qkv);
    cudaGetSymbolAddress((void**)&attn, g_attn);

    const int smem_attn = (3 * 64 * PADQ + 64 * PADV) * (int)sizeof(float); // 70656
    cudaFuncSetAttribute(attn_mma_kernel,
                         cudaFuncAttributeMaxDynamicSharedMemorySize, smem_attn);

    // 1) QKV projection: [4096,1024] @ [1024,3072] + bias  (tf32 MMA)
    gemm_mma_kernel<<<dim3(3 * HID / 128, MTOT / 128), 256>>>(
        x, W_qkv, b_qkv, qkv, MTOT, 3 * HID, HID);

    // 2) Causal attention per (b, h) — tf32 MMA
    attn_mma_kernel<<<dim3(SEQ / 64, NHEAD, BATCH), 128, smem_attn>>>(qkv, attn);

    // 3) Output projection: [4096,1024] @ [1024,1024] + bias  (tf32 MMA)
    gemm_mma_kernel<<<dim3(HID / 128, MTOT / 128), 256>>>(
        attn, W_o, b_o, out, MTOT, HID, HID);
}

// round 4
// speedup vs baseline: 6.7474x; 1.2634x over previous
#include <cuda_runtime.h>
#include <cstdint>

#define HID   1024
#define SEQ   2048
#define BATCH 2
#define NHEAD 16
#define HD    64
#define MTOT  (BATCH * SEQ)   /* 4096 */
#define FILLV (-10000.0f)

#define PADS 68   /* attention: Ss/Ks row pad (words) */
#define PADV 72   /* attention: Vs row pad (words) */

#define BK   16   /* gemm k-slice */
#define GPA  20   /* gemm A smem row stride (words): bank = 4g+tg, conflict-free */
#define GPB  136  /* gemm B smem row stride (words): bank = 8tg+g, conflict-free */

// Scratch (device globals; no runtime allocation allowed)
__device__ float g_qkv[(size_t)MTOT * 3 * HID];     // ~100.7 MB (tf32-rounded)
__device__ float g_attn[(size_t)MTOT * HID];        // ~16.8 MB (tf32-rounded)
__device__ float g_x [(size_t)MTOT * HID];          // tf32-rounded x
__device__ float g_wq[(size_t)HID * 3 * HID];       // tf32-rounded W_qkv
__device__ float g_wo[(size_t)HID * HID];           // tf32-rounded W_o

// ---------------------------------------------------------------------------
// helpers
// ---------------------------------------------------------------------------
__device__ __forceinline__ uint32_t f2tf(float x) {
    uint32_t r;
    asm("cvt.rna.tf32.f32 %0, %1;" : "=r"(r) : "f"(x));
    return r;
}
__device__ __forceinline__ float f2tff(float x) {
    return __uint_as_float(f2tf(x));
}

__device__ __forceinline__ void mma_tf32(float c[4],
    uint32_t a0, uint32_t a1, uint32_t a2, uint32_t a3,
    uint32_t b0, uint32_t b1)
{
    asm volatile(
        "mma.sync.aligned.m16n8k8.row.col.f32.tf32.tf32.f32 "
        "{%0,%1,%2,%3}, {%4,%5,%6,%7}, {%8,%9}, {%0,%1,%2,%3};\n"
        : "+f"(c[0]), "+f"(c[1]), "+f"(c[2]), "+f"(c[3])
        : "r"(a0), "r"(a1), "r"(a2), "r"(a3), "r"(b0), "r"(b1));
}

__device__ __forceinline__ uint32_t smem_u32(const void* p) {
    return (uint32_t)__cvta_generic_to_shared(p);
}
#define CP_ASYNC16(dst, src) \
    asm volatile("cp.async.cg.shared.global [%0], [%1], 16;" :: "r"(dst), "l"(src))
#define CP_COMMIT() asm volatile("cp.async.commit_group;")
#define CP_WAIT1()  asm volatile("cp.async.wait_group 1;")

// ---------------------------------------------------------------------------
// tf32 pre-round: out[i] = round_tf32(in[i])
// ---------------------------------------------------------------------------
__global__ void cvt_tf32_kernel(const float4* __restrict__ in,
                                float4* __restrict__ out, int n4)
{
    int i = blockIdx.x * blockDim.x + threadIdx.x;
    if (i < n4) {
        float4 v = in[i];
        v.x = f2tff(v.x); v.y = f2tff(v.y);
        v.z = f2tff(v.z); v.w = f2tff(v.w);
        out[i] = v;
    }
}

// ---------------------------------------------------------------------------
// C[M,N] = A[M,K] @ W[K,N] + bias[N]   (A, W already tf32-rounded)
// Block 128x128, BK=16, 128 threads (4 warps, warp tile 64x64).
// cp.async double-buffered. Optionally tf32-rounds the output.
// ---------------------------------------------------------------------------
__global__ __launch_bounds__(128, 2) void gemm_mma_kernel(
    const float* __restrict__ A, const float* __restrict__ W,
    const float* __restrict__ bias, float* __restrict__ C,
    int M, int N, int K, int round_out)
{
    __shared__ float As[2][128 * GPA];
    __shared__ float Bs[2][BK * GPB];

    const int t    = threadIdx.x;
    const int warp = t >> 5;
    const int lane = t & 31;
    const int g    = lane >> 2;
    const int tg   = lane & 3;
    const int wm   = (warp & 1) * 64;
    const int wn   = (warp >> 1) * 64;
    const int m0   = blockIdx.y * 128;
    const int n0   = blockIdx.x * 128;

    // load mapping: A: thread t owns row t (4x16B). B: row t>>3, 4x16B strided.
    const float* Arow = A + (size_t)(m0 + t) * K;
    const int    bkr  = t >> 3;
    const int    bn8  = (t & 7) * 4;  // float offset of first chunk

    uint32_t aDst[2], bDst[2];
#pragma unroll
    for (int s = 0; s < 2; s++) {
        aDst[s] = smem_u32(&As[s][t * GPA]);
        bDst[s] = smem_u32(&Bs[s][bkr * GPB]);
    }

    const int iters = K / BK;

    // prologue: stage 0
    {
        const float* a = Arow;
#pragma unroll
        for (int j = 0; j < 4; j++) CP_ASYNC16(aDst[0] + j * 16, a + j * 4);
        const float* brow = W + (size_t)bkr * N + n0;
#pragma unroll
        for (int j = 0; j < 4; j++) {
            const int nf = bn8 + j * 32;
            CP_ASYNC16(bDst[0] + nf * 4, brow + nf);
        }
    }
    CP_COMMIT();

    float c[4][8][4];
#pragma unroll
    for (int mi = 0; mi < 4; mi++)
#pragma unroll
        for (int nt = 0; nt < 8; nt++)
#pragma unroll
            for (int e = 0; e < 4; e++) c[mi][nt][e] = 0.0f;

    for (int it = 0; it < iters; it++) {
        const int cur = it & 1;
        const int nxt = cur ^ 1;

        if (it + 1 < iters) {
            const int k0 = (it + 1) * BK;
            const float* a = Arow + k0;
#pragma unroll
            for (int j = 0; j < 4; j++) CP_ASYNC16(aDst[nxt] + j * 16, a + j * 4);
            const float* brow = W + (size_t)(k0 + bkr) * N + n0;
#pragma unroll
            for (int j = 0; j < 4; j++) {
                const int nf = bn8 + j * 32;
                CP_ASYNC16(bDst[nxt] + nf * 4, brow + nf);
            }
        }
        CP_COMMIT();
        CP_WAIT1();          // tile 'it' resident
        __syncthreads();

#pragma unroll
        for (int k8 = 0; k8 < BK; k8 += 8) {
            uint32_t a0[4], a1[4], a2[4], a3[4];
#pragma unroll
            for (int mi = 0; mi < 4; mi++) {
                const int row = wm + mi * 16;
                a0[mi] = __float_as_uint(As[cur][(row + g)     * GPA + k8 + tg]);
                a1[mi] = __float_as_uint(As[cur][(row + g + 8) * GPA + k8 + tg]);
                a2[mi] = __float_as_uint(As[cur][(row + g)     * GPA + k8 + tg + 4]);
                a3[mi] = __float_as_uint(As[cur][(row + g + 8) * GPA + k8 + tg + 4]);
            }
#pragma unroll
            for (int nt = 0; nt < 8; nt++) {
                const uint32_t b0 =
                    __float_as_uint(Bs[cur][(k8 + tg)     * GPB + wn + nt * 8 + g]);
                const uint32_t b1 =
                    __float_as_uint(Bs[cur][(k8 + tg + 4) * GPB + wn + nt * 8 + g]);
#pragma unroll
                for (int mi = 0; mi < 4; mi++)
                    mma_tf32(c[mi][nt], a0[mi], a1[mi], a2[mi], a3[mi], b0, b1);
            }
        }
        __syncthreads();     // all reads of 'cur' done before it is refilled
    }

    // epilogue
#pragma unroll
    for (int mi = 0; mi < 4; mi++) {
#pragma unroll
        for (int nt = 0; nt < 8; nt++) {
            const int row = m0 + wm + mi * 16 + g;
            const int col = n0 + wn + nt * 8 + tg * 2;
            const float bv0 = bias[col];
            const float bv1 = bias[col + 1];
            float v0 = c[mi][nt][0] + bv0;
            float v1 = c[mi][nt][1] + bv1;
            float v2 = c[mi][nt][2] + bv0;
            float v3 = c[mi][nt][3] + bv1;
            if (round_out) {
                v0 = f2tff(v0); v1 = f2tff(v1);
                v2 = f2tff(v2); v3 = f2tff(v3);
            }
            *reinterpret_cast<float2*>(&C[(size_t)row * N + col]) =
                make_float2(v0, v1);
            *reinterpret_cast<float2*>(&C[(size_t)(row + 8) * N + col]) =
                make_float2(v2, v3);
        }
    }
}

// ---------------------------------------------------------------------------
// Causal flash attention, m16n8k8 tf32 MMA. qkv is pre-rounded to tf32.
// grid = (SEQ/64, NHEAD, BATCH), 128 threads = 4 warps, 2 CTAs/SM.
// Q fragments live in registers; Ss doubles as the Q staging buffer.
// ---------------------------------------------------------------------------
__global__ __launch_bounds__(128, 2) void attn_mma_kernel(
    const float* __restrict__ qkv, float* __restrict__ out)
{
    extern __shared__ float smem[];
    float* Ss = smem;                 // 64*PADS (also Q staging)
    float* Ks = Ss + 64 * PADS;       // 64*PADS
    float* Vs = Ks + 64 * PADS;       // 64*PADV

    const int t    = threadIdx.x;
    const int warp = t >> 5;
    const int lane = t & 31;
    const int g    = lane >> 2;
    const int tg   = lane & 3;

    const int qt = gridDim.x - 1 - blockIdx.x;  // heavy tiles first
    const int h  = blockIdx.y;
    const int b  = blockIdx.z;
    const int q0w = warp * 16;

    // stage Q tile into Ss
    for (int i = t; i < 64 * 16; i += 128) {
        const int row = i >> 4;
        const int dv  = (i & 15) * 4;
        float4 v = *reinterpret_cast<const float4*>(
            &qkv[(size_t)(b * SEQ + qt * 64 + row) * (3 * HID) + h * HD + dv]);
        *reinterpret_cast<float4*>(&Ss[row * PADS + dv]) = v;
    }
    __syncthreads();

    // hoist Q fragments to registers
    uint32_t qa0[8], qa1[8], qa2[8], qa3[8];
#pragma unroll
    for (int ki = 0; ki < 8; ki++) {
        const int k8 = ki * 8;
        qa0[ki] = __float_as_uint(Ss[(q0w + g)     * PADS + k8 + tg]);
        qa1[ki] = __float_as_uint(Ss[(q0w + g + 8) * PADS + k8 + tg]);
        qa2[ki] = __float_as_uint(Ss[(q0w + g)     * PADS + k8 + tg + 4]);
        qa3[ki] = __float_as_uint(Ss[(q0w + g + 8) * PADS + k8 + tg + 4]);
    }

    float mrow0 = -1e30f, mrow1 = -1e30f;
    float lrow0 = 0.0f,   lrow1 = 0.0f;
    float o[8][4];
#pragma unroll
    for (int nt = 0; nt < 8; nt++)
#pragma unroll
        for (int e = 0; e < 4; e++) o[nt][e] = 0.0f;

    const int r0 = qt * 64 + q0w + g;
    const int r1 = r0 + 8;

    for (int kt = 0; kt <= qt; kt++) {
        __syncthreads();  // Q-frag reads done (iter 0) / K,V,Ss consumed (iter>0)

        for (int i = t; i < 64 * 16; i += 128) {
            const int row = i >> 4;
            const int dv  = (i & 15) * 4;
            const size_t base =
                (size_t)(b * SEQ + kt * 64 + row) * (3 * HID) + h * HD + dv;
            float4 k4 = *reinterpret_cast<const float4*>(&qkv[base + HID]);
            *reinterpret_cast<float4*>(&Ks[row * PADS + dv]) = k4;
            float4 v4 = *reinterpret_cast<const float4*>(&qkv[base + 2 * HID]);
            *reinterpret_cast<float4*>(&Vs[row * PADV + dv]) = v4;
        }
        __syncthreads();

        float sc[8][4];
#pragma unroll
        for (int nt = 0; nt < 8; nt++)
#pragma unroll
            for (int e = 0; e < 4; e++) sc[nt][e] = 0.0f;

#pragma unroll
        for (int ki = 0; ki < 8; ki++) {
            const int k8 = ki * 8;
#pragma unroll
            for (int nt = 0; nt < 8; nt++) {
                const uint32_t b0 = __float_as_uint(Ks[(nt * 8 + g) * PADS + k8 + tg]);
                const uint32_t b1 = __float_as_uint(Ks[(nt * 8 + g) * PADS + k8 + tg + 4]);
                mma_tf32(sc[nt], qa0[ki], qa1[ki], qa2[ki], qa3[ki], b0, b1);
            }
        }

        const bool diag = (kt == qt);
        float mx0 = -1e30f, mx1 = -1e30f;
#pragma unroll
        for (int nt = 0; nt < 8; nt++) {
            const int cc = kt * 64 + nt * 8 + tg * 2;
#pragma unroll
            for (int e = 0; e < 4; e++) sc[nt][e] *= 0.125f;
            if (diag) {
                if (cc     > r0) sc[nt][0] = FILLV;
                if (cc + 1 > r0) sc[nt][1] = FILLV;
                if (cc     > r1) sc[nt][2] = FILLV;
                if (cc + 1 > r1) sc[nt][3] = FILLV;
            }
            mx0 = fmaxf(mx0, fmaxf(sc[nt][0], sc[nt][1]));
            mx1 = fmaxf(mx1, fmaxf(sc[nt][2], sc[nt][3]));
        }
        mx0 = fmaxf(mx0, __shfl_xor_sync(0xffffffffu, mx0, 1));
        mx0 = fmaxf(mx0, __shfl_xor_sync(0xffffffffu, mx0, 2));
        mx1 = fmaxf(mx1, __shfl_xor_sync(0xffffffffu, mx1, 1));
        mx1 = fmaxf(mx1, __shfl_xor_sync(0xffffffffu, mx1, 2));

        const float mn0 = fmaxf(mrow0, mx0);
        const float mn1 = fmaxf(mrow1, mx1);
        const float corr0 = __expf(mrow0 - mn0);
        const float corr1 = __expf(mrow1 - mn1);

        float ps0 = 0.0f, ps1 = 0.0f;
#pragma unroll
        for (int nt = 0; nt < 8; nt++) {
            const float p0 = __expf(sc[nt][0] - mn0);
            const float p1 = __expf(sc[nt][1] - mn0);
            const float p2 = __expf(sc[nt][2] - mn1);
            const float p3 = __expf(sc[nt][3] - mn1);
            ps0 += p0 + p1;
            ps1 += p2 + p3;
            *reinterpret_cast<float2*>(&Ss[(q0w + g)     * PADS + nt * 8 + tg * 2]) =
                make_float2(f2tff(p0), f2tff(p1));
            *reinterpret_cast<float2*>(&Ss[(q0w + g + 8) * PADS + nt * 8 + tg * 2]) =
                make_float2(f2tff(p2), f2tff(p3));
        }
        ps0 += __shfl_xor_sync(0xffffffffu, ps0, 1);
        ps0 += __shfl_xor_sync(0xffffffffu, ps0, 2);
        ps1 += __shfl_xor_sync(0xffffffffu, ps1, 1);
        ps1 += __shfl_xor_sync(0xffffffffu, ps1, 2);

        lrow0 = lrow0 * corr0 + ps0;
        lrow1 = lrow1 * corr1 + ps1;
        mrow0 = mn0;
        mrow1 = mn1;
#pragma unroll
        for (int nt = 0; nt < 8; nt++) {
            o[nt][0] *= corr0; o[nt][1] *= corr0;
            o[nt][2] *= corr1; o[nt][3] *= corr1;
        }

        __syncwarp();  // Ss rows are warp-private

#pragma unroll
        for (int k8 = 0; k8 < 64; k8 += 8) {
            const uint32_t a0 = __float_as_uint(Ss[(q0w + g)     * PADS + k8 + tg]);
            const uint32_t a1 = __float_as_uint(Ss[(q0w + g + 8) * PADS + k8 + tg]);
            const uint32_t a2 = __float_as_uint(Ss[(q0w + g)     * PADS + k8 + tg + 4]);
            const uint32_t a3 = __float_as_uint(Ss[(q0w + g + 8) * PADS + k8 + tg + 4]);
#pragma unroll
            for (int nt = 0; nt < 8; nt++) {
                const uint32_t b0 = __float_as_uint(Vs[(k8 + tg)     * PADV + nt * 8 + g]);
                const uint32_t b1 = __float_as_uint(Vs[(k8 + tg + 4) * PADV + nt * 8 + g]);
                mma_tf32(o[nt], a0, a1, a2, a3, b0, b1);
            }
        }
        __syncwarp();
    }

    // output, tf32-rounded so the O-projection needs no cvt
    const float i0 = 1.0f / lrow0;
    const float i1 = 1.0f / lrow1;
    const size_t base0 = (size_t)(b * SEQ + r0) * HID + h * HD;
    const size_t base1 = base0 + (size_t)8 * HID;
#pragma unroll
    for (int nt = 0; nt < 8; nt++) {
        *reinterpret_cast<float2*>(&out[base0 + nt * 8 + tg * 2]) =
            make_float2(f2tff(o[nt][0] * i0), f2tff(o[nt][1] * i0));
        *reinterpret_cast<float2*>(&out[base1 + nt * 8 + tg * 2]) =
            make_float2(f2tff(o[nt][2] * i1), f2tff(o[nt][3] * i1));
    }
}

// ---------------------------------------------------------------------------
extern "C" void kernel_launch(void* const* d_in, const int* in_sizes, int n_in,
                              void* d_out, int out_size)
{
    const float* x     = (const float*)d_in[0];
    const float* W_qkv = (const float*)d_in[1];
    const float* b_qkv = (const float*)d_in[2];
    const float* W_o   = (const float*)d_in[3];
    const float* b_o   = (const float*)d_in[4];
    float* out = (float*)d_out;

    float *qkv, *attn, *xr, *wq, *wo;
    cudaGetSymbolAddress((void**)&qkv,  g_qkv);
    cudaGetSymbolAddress((void**)&attn, g_attn);
    cudaGetSymbolAddress((void**)&xr,   g_x);
    cudaGetSymbolAddress((void**)&wq,   g_wq);
    cudaGetSymbolAddress((void**)&wo,   g_wo);

    const int smem_attn = (2 * 64 * PADS + 64 * PADV) * (int)sizeof(float); // 53248
    cudaFuncSetAttribute(attn_mma_kernel,
                         cudaFuncAttributeMaxDynamicSharedMemorySize, smem_attn);

    // 0) pre-round inputs to tf32
    {
        const int n4x = MTOT * HID / 4;
        const int n4q = HID * 3 * HID / 4;
        const int n4o = HID * HID / 4;
        cvt_tf32_kernel<<<(n4x + 255) / 256, 256>>>((const float4*)x,     (float4*)xr, n4x);
        cvt_tf32_kernel<<<(n4q + 255) / 256, 256>>>((const float4*)W_qkv, (float4*)wq, n4q);
        cvt_tf32_kernel<<<(n4o + 255) / 256, 256>>>((const float4*)W_o,   (float4*)wo, n4o);
    }

    // 1) QKV projection (output tf32-rounded for attention)
    gemm_mma_kernel<<<dim3(3 * HID / 128, MTOT / 128), 128>>>(
        xr, wq, b_qkv, qkv, MTOT, 3 * HID, HID, 1);

    // 2) Causal attention per (b, h)
    attn_mma_kernel<<<dim3(SEQ / 64, NHEAD, BATCH), 128, smem_attn>>>(qkv, attn);

    // 3) Output projection (fp32 output)
    gemm_mma_kernel<<<dim3(HID / 128, MTOT / 128), 128>>>(
        attn, wo, b_o, out, MTOT, HID, HID, 0);
}

// round 5
// speedup vs baseline: 6.8357x; 1.0131x over previous
#include <cuda_runtime.h>
#include <cstdint>

#define HID   1024
#define SEQ   2048
#define BATCH 2
#define NHEAD 16
#define HD    64
#define MTOT  (BATCH * SEQ)   /* 4096 */
#define FILLV (-10000.0f)

#define PADS 68   /* attention: Ss/Ks row pad (words) */
#define PADV 72   /* attention: Vs row pad (words) */

#define BK    16  /* gemm k-slice */
#define GSTG  4   /* gemm cp.async stages */
#define GPA   20  /* gemm A smem row stride (words) */
#define GPB   136 /* gemm B smem row stride (words) */

// Scratch (device globals; no runtime allocation allowed)
__device__ float g_qkv[(size_t)MTOT * 3 * HID];     // tf32-rounded qkv
__device__ float g_attn[(size_t)MTOT * HID];        // tf32-rounded attn out
__device__ float g_x [(size_t)MTOT * HID];          // tf32-rounded x
__device__ float g_wq[(size_t)HID * 3 * HID];       // tf32-rounded W_qkv
__device__ float g_wo[(size_t)HID * HID];           // tf32-rounded W_o

// ---------------------------------------------------------------------------
// helpers
// ---------------------------------------------------------------------------
__device__ __forceinline__ uint32_t f2tf(float x) {
    uint32_t r;
    asm("cvt.rna.tf32.f32 %0, %1;" : "=r"(r) : "f"(x));
    return r;
}
__device__ __forceinline__ float f2tff(float x) {
    return __uint_as_float(f2tf(x));
}

__device__ __forceinline__ void mma_tf32(float c[4],
    uint32_t a0, uint32_t a1, uint32_t a2, uint32_t a3,
    uint32_t b0, uint32_t b1)
{
    asm volatile(
        "mma.sync.aligned.m16n8k8.row.col.f32.tf32.tf32.f32 "
        "{%0,%1,%2,%3}, {%4,%5,%6,%7}, {%8,%9}, {%0,%1,%2,%3};\n"
        : "+f"(c[0]), "+f"(c[1]), "+f"(c[2]), "+f"(c[3])
        : "r"(a0), "r"(a1), "r"(a2), "r"(a3), "r"(b0), "r"(b1));
}

__device__ __forceinline__ uint32_t smem_u32(const void* p) {
    return (uint32_t)__cvta_generic_to_shared(p);
}
#define CP_ASYNC16(dst, src) \
    asm volatile("cp.async.cg.shared.global [%0], [%1], 16;" :: "r"(dst), "l"(src))
#define CP_COMMIT() asm volatile("cp.async.commit_group;")
#define CP_WAIT0()  asm volatile("cp.async.wait_group 0;")
#define CP_WAIT2()  asm volatile("cp.async.wait_group 2;")

// ---------------------------------------------------------------------------
// tf32 pre-round
// ---------------------------------------------------------------------------
__global__ void cvt_tf32_kernel(const float4* __restrict__ in,
                                float4* __restrict__ out, int n4)
{
    int i = blockIdx.x * blockDim.x + threadIdx.x;
    if (i < n4) {
        float4 v = in[i];
        v.x = f2tff(v.x); v.y = f2tff(v.y);
        v.z = f2tff(v.z); v.w = f2tff(v.w);
        out[i] = v;
    }
}

// ---------------------------------------------------------------------------
// C[M,N] = A[M,K] @ W[K,N] + bias[N]   (A, W pre-rounded to tf32)
// Block 128x128, BK=16, 128 threads (4 warps, 64x64 warp tile).
// 4-stage cp.async ring, ONE __syncthreads per k-slice.
// ---------------------------------------------------------------------------
__global__ __launch_bounds__(128, 2) void gemm_mma_kernel(
    const float* __restrict__ A, const float* __restrict__ W,
    const float* __restrict__ bias, float* __restrict__ C,
    int M, int N, int K, int round_out)
{
    extern __shared__ float smem[];
    float* As = smem;                       // GSTG * 128 * GPA
    float* Bs = As + GSTG * 128 * GPA;      // GSTG * BK * GPB

    const int t    = threadIdx.x;
    const int warp = t >> 5;
    const int lane = t & 31;
    const int g    = lane >> 2;
    const int tg   = lane & 3;
    const int wm   = (warp & 1) * 64;
    const int wn   = (warp >> 1) * 64;
    const int m0   = blockIdx.y * 128;
    const int n0   = blockIdx.x * 128;

    const float* Arow = A + (size_t)(m0 + t) * K;
    const int    bkr  = t >> 3;
    const int    bn8  = (t & 7) * 4;

    uint32_t aDst[GSTG], bDst[GSTG];
#pragma unroll
    for (int s = 0; s < GSTG; s++) {
        aDst[s] = smem_u32(&As[s * 128 * GPA + t * GPA]);
        bDst[s] = smem_u32(&Bs[s * BK * GPB + bkr * GPB]);
    }

    const int iters = K / BK;

    // prologue: stages 0..GSTG-2 (one committed group each)
#pragma unroll
    for (int s = 0; s < GSTG - 1; s++) {
        const int k0 = s * BK;
        const float* a = Arow + k0;
#pragma unroll
        for (int j = 0; j < 4; j++) CP_ASYNC16(aDst[s] + j * 16, a + j * 4);
        const float* brow = W + (size_t)(k0 + bkr) * N + n0;
#pragma unroll
        for (int j = 0; j < 4; j++) {
            const int nf = bn8 + j * 32;
            CP_ASYNC16(bDst[s] + nf * 4, brow + nf);
        }
        CP_COMMIT();
    }

    float c[4][8][4];
#pragma unroll
    for (int mi = 0; mi < 4; mi++)
#pragma unroll
        for (int nt = 0; nt < 8; nt++)
#pragma unroll
            for (int e = 0; e < 4; e++) c[mi][nt][e] = 0.0f;

    for (int it = 0; it < iters; it++) {
        const int cur = it & (GSTG - 1);

        CP_WAIT2();          // group arithmetic: stage 'it' resident
        __syncthreads();     // visible to all; prior reads of reuse buffer done

        // issue stage it+GSTG-1 (overlaps compute below)
        if (it + GSTG - 1 < iters) {
            const int s  = (it + GSTG - 1) & (GSTG - 1);
            const int k0 = (it + GSTG - 1) * BK;
            const float* a = Arow + k0;
#pragma unroll
            for (int j = 0; j < 4; j++) CP_ASYNC16(aDst[s] + j * 16, a + j * 4);
            const float* brow = W + (size_t)(k0 + bkr) * N + n0;
#pragma unroll
            for (int j = 0; j < 4; j++) {
                const int nf = bn8 + j * 32;
                CP_ASYNC16(bDst[s] + nf * 4, brow + nf);
            }
        }
        CP_COMMIT();         // always commit: keeps one group per iter

        const float* Ac = &As[cur * 128 * GPA];
        const float* Bc = &Bs[cur * BK * GPB];
#pragma unroll
        for (int k8 = 0; k8 < BK; k8 += 8) {
            uint32_t a0[4], a1[4], a2[4], a3[4];
#pragma unroll
            for (int mi = 0; mi < 4; mi++) {
                const int row = wm + mi * 16;
                a0[mi] = __float_as_uint(Ac[(row + g)     * GPA + k8 + tg]);
                a1[mi] = __float_as_uint(Ac[(row + g + 8) * GPA + k8 + tg]);
                a2[mi] = __float_as_uint(Ac[(row + g)     * GPA + k8 + tg + 4]);
                a3[mi] = __float_as_uint(Ac[(row + g + 8) * GPA + k8 + tg + 4]);
            }
#pragma unroll
            for (int nt = 0; nt < 8; nt++) {
                const uint32_t b0 =
                    __float_as_uint(Bc[(k8 + tg)     * GPB + wn + nt * 8 + g]);
                const uint32_t b1 =
                    __float_as_uint(Bc[(k8 + tg + 4) * GPB + wn + nt * 8 + g]);
#pragma unroll
                for (int mi = 0; mi < 4; mi++)
                    mma_tf32(c[mi][nt], a0[mi], a1[mi], a2[mi], a3[mi], b0, b1);
            }
        }
    }

    // epilogue
#pragma unroll
    for (int mi = 0; mi < 4; mi++) {
#pragma unroll
        for (int nt = 0; nt < 8; nt++) {
            const int row = m0 + wm + mi * 16 + g;
            const int col = n0 + wn + nt * 8 + tg * 2;
            const float bv0 = bias[col];
            const float bv1 = bias[col + 1];
            float v0 = c[mi][nt][0] + bv0;
            float v1 = c[mi][nt][1] + bv1;
            float v2 = c[mi][nt][2] + bv0;
            float v3 = c[mi][nt][3] + bv1;
            if (round_out) {
                v0 = f2tff(v0); v1 = f2tff(v1);
                v2 = f2tff(v2); v3 = f2tff(v3);
            }
            *reinterpret_cast<float2*>(&C[(size_t)row * N + col]) =
                make_float2(v0, v1);
            *reinterpret_cast<float2*>(&C[(size_t)(row + 8) * N + col]) =
                make_float2(v2, v3);
        }
    }
}

// ---------------------------------------------------------------------------
// Causal flash attention, m16n8k8 tf32 MMA, cp.async double-buffered K/V.
// grid = (SEQ/64, NHEAD, BATCH), 128 threads = 4 warps, 2 CTAs/SM.
// ---------------------------------------------------------------------------
__global__ __launch_bounds__(128, 2) void attn_mma_kernel(
    const float* __restrict__ qkv, float* __restrict__ out)
{
    extern __shared__ float smem[];
    float* Ss = smem;                        // 64*PADS (also Q staging)
    float* Ks = Ss + 64 * PADS;              // 2 stages of 64*PADS
    float* Vs = Ks + 2 * 64 * PADS;          // 2 stages of 64*PADV

    const int t    = threadIdx.x;
    const int warp = t >> 5;
    const int lane = t & 31;
    const int g    = lane >> 2;
    const int tg   = lane & 3;

    const int qt = gridDim.x - 1 - blockIdx.x;  // heavy tiles first
    const int h  = blockIdx.y;
    const int b  = blockIdx.z;
    const int q0w = warp * 16;

    // per-thread K/V load slice: 8 chunks of 16B each per tile
    const int lrow = t >> 4;          // 0..7 base row
    const int ldv  = (t & 15) * 4;    // 0..60 float offset

    // stage Q tile into Ss
    for (int i = t; i < 64 * 16; i += 128) {
        const int row = i >> 4;
        const int dv  = (i & 15) * 4;
        float4 v = *reinterpret_cast<const float4*>(
            &qkv[(size_t)(b * SEQ + qt * 64 + row) * (3 * HID) + h * HD + dv]);
        *reinterpret_cast<float4*>(&Ss[row * PADS + dv]) = v;
    }
    __syncthreads();

    // hoist Q fragments to registers
    uint32_t qa0[8], qa1[8], qa2[8], qa3[8];
#pragma unroll
    for (int ki = 0; ki < 8; ki++) {
        const int k8 = ki * 8;
        qa0[ki] = __float_as_uint(Ss[(q0w + g)     * PADS + k8 + tg]);
        qa1[ki] = __float_as_uint(Ss[(q0w + g + 8) * PADS + k8 + tg]);
        qa2[ki] = __float_as_uint(Ss[(q0w + g)     * PADS + k8 + tg + 4]);
        qa3[ki] = __float_as_uint(Ss[(q0w + g + 8) * PADS + k8 + tg + 4]);
    }
    __syncthreads();   // Q frag reads done before Ss is reused for P

    // prologue: issue K/V for kt=0 into stage 0
    {
        const size_t tb = (size_t)(b * SEQ) * (3 * HID) + h * HD;
#pragma unroll
        for (int j = 0; j < 8; j++) {
            const int row = lrow + j * 8;
            const size_t src = tb + (size_t)row * (3 * HID) + ldv;
            CP_ASYNC16(smem_u32(&Ks[row * PADS + ldv]), &qkv[src + HID]);
            CP_ASYNC16(smem_u32(&Vs[row * PADV + ldv]), &qkv[src + 2 * HID]);
        }
        CP_COMMIT();
    }

    float mrow0 = -1e30f, mrow1 = -1e30f;
    float lrow0f = 0.0f,  lrow1f = 0.0f;
    float o[8][4];
#pragma unroll
    for (int nt = 0; nt < 8; nt++)
#pragma unroll
        for (int e = 0; e < 4; e++) o[nt][e] = 0.0f;

    const int r0 = qt * 64 + q0w + g;
    const int r1 = r0 + 8;

    for (int kt = 0; kt <= qt; kt++) {
        const int cur = kt & 1;

        CP_WAIT0();        // stage cur resident (issue of kt+1 comes after)
        __syncthreads();   // visible to all; prior P/V reads complete

        // issue K/V for kt+1 into the other stage (overlaps compute)
        if (kt + 1 <= qt) {
            const int nxt = cur ^ 1;
            const size_t tb =
                (size_t)(b * SEQ + (kt + 1) * 64) * (3 * HID) + h * HD;
#pragma unroll
            for (int j = 0; j < 8; j++) {
                const int row = lrow + j * 8;
                const size_t src = tb + (size_t)row * (3 * HID) + ldv;
                CP_ASYNC16(smem_u32(&Ks[(nxt * 64 + row) * PADS + ldv]),
                           &qkv[src + HID]);
                CP_ASYNC16(smem_u32(&Vs[(nxt * 64 + row) * PADV + ldv]),
                           &qkv[src + 2 * HID]);
            }
        }
        CP_COMMIT();

        const float* Kc = &Ks[cur * 64 * PADS];
        const float* Vc = &Vs[cur * 64 * PADV];

        float sc[8][4];
#pragma unroll
        for (int nt = 0; nt < 8; nt++)
#pragma unroll
            for (int e = 0; e < 4; e++) sc[nt][e] = 0.0f;

#pragma unroll
        for (int ki = 0; ki < 8; ki++) {
            const int k8 = ki * 8;
#pragma unroll
            for (int nt = 0; nt < 8; nt++) {
                const uint32_t b0 = __float_as_uint(Kc[(nt * 8 + g) * PADS + k8 + tg]);
                const uint32_t b1 = __float_as_uint(Kc[(nt * 8 + g) * PADS + k8 + tg + 4]);
                mma_tf32(sc[nt], qa0[ki], qa1[ki], qa2[ki], qa3[ki], b0, b1);
            }
        }

        const bool diag = (kt == qt);
        float mx0 = -1e30f, mx1 = -1e30f;
#pragma unroll
        for (int nt = 0; nt < 8; nt++) {
            const int cc = kt * 64 + nt * 8 + tg * 2;
#pragma unroll
            for (int e = 0; e < 4; e++) sc[nt][e] *= 0.125f;
            if (diag) {
                if (cc     > r0) sc[nt][0] = FILLV;
                if (cc + 1 > r0) sc[nt][1] = FILLV;
                if (cc     > r1) sc[nt][2] = FILLV;
                if (cc + 1 > r1) sc[nt][3] = FILLV;
            }
            mx0 = fmaxf(mx0, fmaxf(sc[nt][0], sc[nt][1]));
            mx1 = fmaxf(mx1, fmaxf(sc[nt][2], sc[nt][3]));
        }
        mx0 = fmaxf(mx0, __shfl_xor_sync(0xffffffffu, mx0, 1));
        mx0 = fmaxf(mx0, __shfl_xor_sync(0xffffffffu, mx0, 2));
        mx1 = fmaxf(mx1, __shfl_xor_sync(0xffffffffu, mx1, 1));
        mx1 = fmaxf(mx1, __shfl_xor_sync(0xffffffffu, mx1, 2));

        const float mn0 = fmaxf(mrow0, mx0);
        const float mn1 = fmaxf(mrow1, mx1);
        const float corr0 = __expf(mrow0 - mn0);
        const float corr1 = __expf(mrow1 - mn1);

        float ps0 = 0.0f, ps1 = 0.0f;
#pragma unroll
        for (int nt = 0; nt < 8; nt++) {
            const float p0 = __expf(sc[nt][0] - mn0);
            const float p1 = __expf(sc[nt][1] - mn0);
            const float p2 = __expf(sc[nt][2] - mn1);
            const float p3 = __expf(sc[nt][3] - mn1);
            ps0 += p0 + p1;
            ps1 += p2 + p3;
            *reinterpret_cast<float2*>(&Ss[(q0w + g)     * PADS + nt * 8 + tg * 2]) =
                make_float2(f2tff(p0), f2tff(p1));
            *reinterpret_cast<float2*>(&Ss[(q0w + g + 8) * PADS + nt * 8 + tg * 2]) =
                make_float2(f2tff(p2), f2tff(p3));
        }
        ps0 += __shfl_xor_sync(0xffffffffu, ps0, 1);
        ps0 += __shfl_xor_sync(0xffffffffu, ps0, 2);
        ps1 += __shfl_xor_sync(0xffffffffu, ps1, 1);
        ps1 += __shfl_xor_sync(0xffffffffu, ps1, 2);

        lrow0f = lrow0f * corr0 + ps0;
        lrow1f = lrow1f * corr1 + ps1;
        mrow0 = mn0;
        mrow1 = mn1;
#pragma unroll
        for (int nt = 0; nt < 8; nt++) {
            o[nt][0] *= corr0; o[nt][1] *= corr0;
            o[nt][2] *= corr1; o[nt][3] *= corr1;
        }

        __syncwarp();  // Ss rows warp-private

#pragma unroll
        for (int k8 = 0; k8 < 64; k8 += 8) {
            const uint32_t a0 = __float_as_uint(Ss[(q0w + g)     * PADS + k8 + tg]);
            const uint32_t a1 = __float_as_uint(Ss[(q0w + g + 8) * PADS + k8 + tg]);
            const uint32_t a2 = __float_as_uint(Ss[(q0w + g)     * PADS + k8 + tg + 4]);
            const uint32_t a3 = __float_as_uint(Ss[(q0w + g + 8) * PADS + k8 + tg + 4]);
#pragma unroll
            for (int nt = 0; nt < 8; nt++) {
                const uint32_t b0 = __float_as_uint(Vc[(k8 + tg)     * PADV + nt * 8 + g]);
                const uint32_t b1 = __float_as_uint(Vc[(k8 + tg + 4) * PADV + nt * 8 + g]);
                mma_tf32(o[nt], a0, a1, a2, a3, b0, b1);
            }
        }
    }

    const float i0 = 1.0f / lrow0f;
    const float i1 = 1.0f / lrow1f;
    const size_t base0 = (size_t)(b * SEQ + r0) * HID + h * HD;
    const size_t base1 = base0 + (size_t)8 * HID;
#pragma unroll
    for (int nt = 0; nt < 8; nt++) {
        *reinterpret_cast<float2*>(&out[base0 + nt * 8 + tg * 2]) =
            make_float2(f2tff(o[nt][0] * i0), f2tff(o[nt][1] * i0));
        *reinterpret_cast<float2*>(&out[base1 + nt * 8 + tg * 2]) =
            make_float2(f2tff(o[nt][2] * i1), f2tff(o[nt][3] * i1));
    }
}

// ---------------------------------------------------------------------------
extern "C" void kernel_launch(void* const* d_in, const int* in_sizes, int n_in,
                              void* d_out, int out_size)
{
    const float* x     = (const float*)d_in[0];
    const float* W_qkv = (const float*)d_in[1];
    const float* b_qkv = (const float*)d_in[2];
    const float* W_o   = (const float*)d_in[3];
    const float* b_o   = (const float*)d_in[4];
    float* out = (float*)d_out;

    float *qkv, *attn, *xr, *wq, *wo;
    cudaGetSymbolAddress((void**)&qkv,  g_qkv);
    cudaGetSymbolAddress((void**)&attn, g_attn);
    cudaGetSymbolAddress((void**)&xr,   g_x);
    cudaGetSymbolAddress((void**)&wq,   g_wq);
    cudaGetSymbolAddress((void**)&wo,   g_wo);

    const int smem_gemm =
        (GSTG * 128 * GPA + GSTG * BK * GPB) * (int)sizeof(float);   // 75776
    const int smem_attn =
        (64 * PADS + 2 * 64 * PADS + 2 * 64 * PADV) * (int)sizeof(float); // 89088
    cudaFuncSetAttribute(gemm_mma_kernel,
                         cudaFuncAttributeMaxDynamicSharedMemorySize, smem_gemm);
    cudaFuncSetAttribute(attn_mma_kernel,
                         cudaFuncAttributeMaxDynamicSharedMemorySize, smem_attn);

    // 0) pre-round inputs to tf32
    {
        const int n4x = MTOT * HID / 4;
        const int n4q = HID * 3 * HID / 4;
        const int n4o = HID * HID / 4;
        cvt_tf32_kernel<<<(n4x + 255) / 256, 256>>>((const float4*)x,     (float4*)xr, n4x);
        cvt_tf32_kernel<<<(n4q + 255) / 256, 256>>>((const float4*)W_qkv, (float4*)wq, n4q);
        cvt_tf32_kernel<<<(n4o + 255) / 256, 256>>>((const float4*)W_o,   (float4*)wo, n4o);
    }

    // 1) QKV projection (output tf32-rounded)
    gemm_mma_kernel<<<dim3(3 * HID / 128, MTOT / 128), 128, smem_gemm>>>(
        xr, wq, b_qkv, qkv, MTOT, 3 * HID, HID, 1);

    // 2) Causal attention
    attn_mma_kernel<<<dim3(SEQ / 64, NHEAD, BATCH), 128, smem_attn>>>(qkv, attn);

    // 3) Output projection (fp32 output)
    gemm_mma_kernel<<<dim3(HID / 128, MTOT / 128), 128, smem_gemm>>>(
        attn, wo, b_o, out, MTOT, HID, HID, 0);
}

// round 6
// speedup vs baseline: 7.0760x; 1.0352x over previous
#include <cuda_runtime.h>
#include <cstdint>

#define HID   1024
#define SEQ   2048
#define BATCH 2
#define NHEAD 16
#define HD    64
#define MTOT  (BATCH * SEQ)   /* 4096 */
#define FILLV (-10000.0f)

#define PADS 68   /* attention: Ss/Ks row pad (words) */
#define PADV 72   /* attention: Vs row pad (words) */

#define BK    16  /* gemm k-slice */
#define GSTG  4   /* gemm cp.async stages */
#define GPA   20  /* gemm A smem row stride (words) */
#define GPB   136 /* gemm B smem row stride (words) */

// Scratch (device globals; no runtime allocation allowed)
__device__ float g_qkv[(size_t)MTOT * 3 * HID];     // tf32-rounded qkv
__device__ float g_attn[(size_t)MTOT * HID];        // tf32-rounded attn out
__device__ float g_x [(size_t)MTOT * HID];          // tf32-rounded x
__device__ float g_wq[(size_t)HID * 3 * HID];       // tf32-rounded W_qkv
__device__ float g_wo[(size_t)HID * HID];           // tf32-rounded W_o

// ---------------------------------------------------------------------------
// helpers
// ---------------------------------------------------------------------------
__device__ __forceinline__ uint32_t f2tf(float x) {
    uint32_t r;
    asm("cvt.rna.tf32.f32 %0, %1;" : "=r"(r) : "f"(x));
    return r;
}
__device__ __forceinline__ float f2tff(float x) {
    return __uint_as_float(f2tf(x));
}

__device__ __forceinline__ void mma_tf32(float c[4],
    uint32_t a0, uint32_t a1, uint32_t a2, uint32_t a3,
    uint32_t b0, uint32_t b1)
{
    asm volatile(
        "mma.sync.aligned.m16n8k8.row.col.f32.tf32.tf32.f32 "
        "{%0,%1,%2,%3}, {%4,%5,%6,%7}, {%8,%9}, {%0,%1,%2,%3};\n"
        : "+f"(c[0]), "+f"(c[1]), "+f"(c[2]), "+f"(c[3])
        : "r"(a0), "r"(a1), "r"(a2), "r"(a3), "r"(b0), "r"(b1));
}

__device__ __forceinline__ uint32_t smem_u32(const void* p) {
    return (uint32_t)__cvta_generic_to_shared(p);
}
#define CP_ASYNC16(dst, src) \
    asm volatile("cp.async.cg.shared.global [%0], [%1], 16;" :: "r"(dst), "l"(src))
#define CP_COMMIT() asm volatile("cp.async.commit_group;")
#define CP_WAIT0()  asm volatile("cp.async.wait_group 0;")
#define CP_WAIT2()  asm volatile("cp.async.wait_group 2;")

// ---------------------------------------------------------------------------
// tf32 pre-round
// ---------------------------------------------------------------------------
__global__ void cvt_tf32_kernel(const float4* __restrict__ in,
                                float4* __restrict__ out, int n4)
{
    int i = blockIdx.x * blockDim.x + threadIdx.x;
    if (i < n4) {
        float4 v = in[i];
        v.x = f2tff(v.x); v.y = f2tff(v.y);
        v.z = f2tff(v.z); v.w = f2tff(v.w);
        out[i] = v;
    }
}

// ---------------------------------------------------------------------------
// C[M,N] = A[M,K] @ W[K,N] + bias[N]   (A, W pre-rounded to tf32)
// Block 128x128, BK=16, 256 threads (8 warps, 32x64 warp tile: 4 m x 2 n).
// 4-stage cp.async ring, ONE __syncthreads per k-slice. 2 CTAs/SM -> 16 warps.
// ---------------------------------------------------------------------------
__global__ __launch_bounds__(256, 2) void gemm_mma_kernel(
    const float* __restrict__ A, const float* __restrict__ W,
    const float* __restrict__ bias, float* __restrict__ C,
    int M, int N, int K, int round_out)
{
    extern __shared__ float smem[];
    float* As = smem;                       // GSTG * 128 * GPA
    float* Bs = As + GSTG * 128 * GPA;      // GSTG * BK * GPB

    const int t    = threadIdx.x;
    const int warp = t >> 5;
    const int lane = t & 31;
    const int g    = lane >> 2;
    const int tg   = lane & 3;
    const int wm   = (warp & 3) * 32;       // 4 warps in m
    const int wn   = (warp >> 2) * 64;      // 2 warps in n
    const int m0   = blockIdx.y * 128;
    const int n0   = blockIdx.x * 128;

    // global-load mapping (256 threads, 2 x 16B chunks each for A and B)
    const int ar = t >> 1;            // A row 0..127
    const int ac = (t & 1) * 8;       // A k float-offset 0/8
    const int br = t >> 4;            // B k-row 0..15
    const int bc = (t & 15) * 8;      // B n float-offset 0..120

    const float* Arow = A + (size_t)(m0 + ar) * K + ac;

    uint32_t aDst[GSTG], bDst[GSTG];
#pragma unroll
    for (int s = 0; s < GSTG; s++) {
        aDst[s] = smem_u32(&As[s * 128 * GPA + ar * GPA + ac]);
        bDst[s] = smem_u32(&Bs[s * BK * GPB + br * GPB + bc]);
    }

    const int iters = K / BK;

    // prologue: stages 0..GSTG-2 (one committed group each)
#pragma unroll
    for (int s = 0; s < GSTG - 1; s++) {
        const int k0 = s * BK;
        const float* a = Arow + k0;
        CP_ASYNC16(aDst[s],      a);
        CP_ASYNC16(aDst[s] + 16, a + 4);
        const float* brow = W + (size_t)(k0 + br) * N + n0 + bc;
        CP_ASYNC16(bDst[s],      brow);
        CP_ASYNC16(bDst[s] + 16, brow + 4);
        CP_COMMIT();
    }

    float c[2][8][4];
#pragma unroll
    for (int mi = 0; mi < 2; mi++)
#pragma unroll
        for (int nt = 0; nt < 8; nt++)
#pragma unroll
            for (int e = 0; e < 4; e++) c[mi][nt][e] = 0.0f;

    for (int it = 0; it < iters; it++) {
        const int cur = it & (GSTG - 1);

        CP_WAIT2();          // stage 'it' resident
        __syncthreads();     // visible to all; prior reads of reuse buffer done

        // issue stage it+GSTG-1 (overlaps compute below)
        if (it + GSTG - 1 < iters) {
            const int s  = (it + GSTG - 1) & (GSTG - 1);
            const int k0 = (it + GSTG - 1) * BK;
            const float* a = Arow + k0;
            CP_ASYNC16(aDst[s],      a);
            CP_ASYNC16(aDst[s] + 16, a + 4);
            const float* brow = W + (size_t)(k0 + br) * N + n0 + bc;
            CP_ASYNC16(bDst[s],      brow);
            CP_ASYNC16(bDst[s] + 16, brow + 4);
        }
        CP_COMMIT();         // always commit: keeps one group per iter

        const float* Ac = &As[cur * 128 * GPA];
        const float* Bc = &Bs[cur * BK * GPB];
#pragma unroll
        for (int k8 = 0; k8 < BK; k8 += 8) {
            uint32_t a0[2], a1[2], a2[2], a3[2];
#pragma unroll
            for (int mi = 0; mi < 2; mi++) {
                const int row = wm + mi * 16;
                a0[mi] = __float_as_uint(Ac[(row + g)     * GPA + k8 + tg]);
                a1[mi] = __float_as_uint(Ac[(row + g + 8) * GPA + k8 + tg]);
                a2[mi] = __float_as_uint(Ac[(row + g)     * GPA + k8 + tg + 4]);
                a3[mi] = __float_as_uint(Ac[(row + g + 8) * GPA + k8 + tg + 4]);
            }
#pragma unroll
            for (int nt = 0; nt < 8; nt++) {
                const uint32_t b0 =
                    __float_as_uint(Bc[(k8 + tg)     * GPB + wn + nt * 8 + g]);
                const uint32_t b1 =
                    __float_as_uint(Bc[(k8 + tg + 4) * GPB + wn + nt * 8 + g]);
                mma_tf32(c[0][nt], a0[0], a1[0], a2[0], a3[0], b0, b1);
                mma_tf32(c[1][nt], a0[1], a1[1], a2[1], a3[1], b0, b1);
            }
        }
    }

    // epilogue
#pragma unroll
    for (int mi = 0; mi < 2; mi++) {
#pragma unroll
        for (int nt = 0; nt < 8; nt++) {
            const int row = m0 + wm + mi * 16 + g;
            const int col = n0 + wn + nt * 8 + tg * 2;
            const float bv0 = bias[col];
            const float bv1 = bias[col + 1];
            float v0 = c[mi][nt][0] + bv0;
            float v1 = c[mi][nt][1] + bv1;
            float v2 = c[mi][nt][2] + bv0;
            float v3 = c[mi][nt][3] + bv1;
            if (round_out) {
                v0 = f2tff(v0); v1 = f2tff(v1);
                v2 = f2tff(v2); v3 = f2tff(v3);
            }
            *reinterpret_cast<float2*>(&C[(size_t)row * N + col]) =
                make_float2(v0, v1);
            *reinterpret_cast<float2*>(&C[(size_t)(row + 8) * N + col]) =
                make_float2(v2, v3);
        }
    }
}

// ---------------------------------------------------------------------------
// Causal flash attention, m16n8k8 tf32 MMA, cp.async double-buffered K/V.
// grid = (SEQ/64, NHEAD, BATCH), 128 threads = 4 warps, 2 CTAs/SM.
// ---------------------------------------------------------------------------
__global__ __launch_bounds__(128, 2) void attn_mma_kernel(
    const float* __restrict__ qkv, float* __restrict__ out)
{
    extern __shared__ float smem[];
    float* Ss = smem;                        // 64*PADS (also Q staging)
    float* Ks = Ss + 64 * PADS;              // 2 stages of 64*PADS
    float* Vs = Ks + 2 * 64 * PADS;          // 2 stages of 64*PADV

    const int t    = threadIdx.x;
    const int warp = t >> 5;
    const int lane = t & 31;
    const int g    = lane >> 2;
    const int tg   = lane & 3;

    const int qt = gridDim.x - 1 - blockIdx.x;  // heavy tiles first
    const int h  = blockIdx.y;
    const int b  = blockIdx.z;
    const int q0w = warp * 16;

    // per-thread K/V load slice: 8 chunks of 16B each per tile
    const int lrow = t >> 4;          // 0..7 base row
    const int ldv  = (t & 15) * 4;    // 0..60 float offset

    // stage Q tile into Ss
    for (int i = t; i < 64 * 16; i += 128) {
        const int row = i >> 4;
        const int dv  = (i & 15) * 4;
        float4 v = *reinterpret_cast<const float4*>(
            &qkv[(size_t)(b * SEQ + qt * 64 + row) * (3 * HID) + h * HD + dv]);
        *reinterpret_cast<float4*>(&Ss[row * PADS + dv]) = v;
    }
    __syncthreads();

    // hoist Q fragments to registers
    uint32_t qa0[8], qa1[8], qa2[8], qa3[8];
#pragma unroll
    for (int ki = 0; ki < 8; ki++) {
        const int k8 = ki * 8;
        qa0[ki] = __float_as_uint(Ss[(q0w + g)     * PADS + k8 + tg]);
        qa1[ki] = __float_as_uint(Ss[(q0w + g + 8) * PADS + k8 + tg]);
        qa2[ki] = __float_as_uint(Ss[(q0w + g)     * PADS + k8 + tg + 4]);
        qa3[ki] = __float_as_uint(Ss[(q0w + g + 8) * PADS + k8 + tg + 4]);
    }
    __syncthreads();   // Q frag reads done before Ss is reused for P

    // prologue: issue K/V for kt=0 into stage 0
    {
        const size_t tb = (size_t)(b * SEQ) * (3 * HID) + h * HD;
#pragma unroll
        for (int j = 0; j < 8; j++) {
            const int row = lrow + j * 8;
            const size_t src = tb + (size_t)row * (3 * HID) + ldv;
            CP_ASYNC16(smem_u32(&Ks[row * PADS + ldv]), &qkv[src + HID]);
            CP_ASYNC16(smem_u32(&Vs[row * PADV + ldv]), &qkv[src + 2 * HID]);
        }
        CP_COMMIT();
    }

    float mrow0 = -1e30f, mrow1 = -1e30f;
    float lrow0f = 0.0f,  lrow1f = 0.0f;
    float o[8][4];
#pragma unroll
    for (int nt = 0; nt < 8; nt++)
#pragma unroll
        for (int e = 0; e < 4; e++) o[nt][e] = 0.0f;

    const int r0 = qt * 64 + q0w + g;
    const int r1 = r0 + 8;

    for (int kt = 0; kt <= qt; kt++) {
        const int cur = kt & 1;

        CP_WAIT0();        // stage cur resident
        __syncthreads();   // visible to all; prior P/V reads complete

        // issue K/V for kt+1 into the other stage (overlaps compute)
        if (kt + 1 <= qt) {
            const int nxt = cur ^ 1;
            const size_t tb =
                (size_t)(b * SEQ + (kt + 1) * 64) * (3 * HID) + h * HD;
#pragma unroll
            for (int j = 0; j < 8; j++) {
                const int row = lrow + j * 8;
                const size_t src = tb + (size_t)row * (3 * HID) + ldv;
                CP_ASYNC16(smem_u32(&Ks[(nxt * 64 + row) * PADS + ldv]),
                           &qkv[src + HID]);
                CP_ASYNC16(smem_u32(&Vs[(nxt * 64 + row) * PADV + ldv]),
                           &qkv[src + 2 * HID]);
            }
        }
        CP_COMMIT();

        const float* Kc = &Ks[cur * 64 * PADS];
        const float* Vc = &Vs[cur * 64 * PADV];

        float sc[8][4];
#pragma unroll
        for (int nt = 0; nt < 8; nt++)
#pragma unroll
            for (int e = 0; e < 4; e++) sc[nt][e] = 0.0f;

#pragma unroll
        for (int ki = 0; ki < 8; ki++) {
            const int k8 = ki * 8;
#pragma unroll
            for (int nt = 0; nt < 8; nt++) {
                const uint32_t b0 = __float_as_uint(Kc[(nt * 8 + g) * PADS + k8 + tg]);
                const uint32_t b1 = __float_as_uint(Kc[(nt * 8 + g) * PADS + k8 + tg + 4]);
                mma_tf32(sc[nt], qa0[ki], qa1[ki], qa2[ki], qa3[ki], b0, b1);
            }
        }

        const bool diag = (kt == qt);
        float mx0 = -1e30f, mx1 = -1e30f;
#pragma unroll
        for (int nt = 0; nt < 8; nt++) {
            const int cc = kt * 64 + nt * 8 + tg * 2;
#pragma unroll
            for (int e = 0; e < 4; e++) sc[nt][e] *= 0.125f;
            if (diag) {
                if (cc     > r0) sc[nt][0] = FILLV;
                if (cc + 1 > r0) sc[nt][1] = FILLV;
                if (cc     > r1) sc[nt][2] = FILLV;
                if (cc + 1 > r1) sc[nt][3] = FILLV;
            }
            mx0 = fmaxf(mx0, fmaxf(sc[nt][0], sc[nt][1]));
            mx1 = fmaxf(mx1, fmaxf(sc[nt][2], sc[nt][3]));
        }
        mx0 = fmaxf(mx0, __shfl_xor_sync(0xffffffffu, mx0, 1));
        mx0 = fmaxf(mx0, __shfl_xor_sync(0xffffffffu, mx0, 2));
        mx1 = fmaxf(mx1, __shfl_xor_sync(0xffffffffu, mx1, 1));
        mx1 = fmaxf(mx1, __shfl_xor_sync(0xffffffffu, mx1, 2));

        const float mn0 = fmaxf(mrow0, mx0);
        const float mn1 = fmaxf(mrow1, mx1);
        const float corr0 = __expf(mrow0 - mn0);
        const float corr1 = __expf(mrow1 - mn1);

        float ps0 = 0.0f, ps1 = 0.0f;
#pragma unroll
        for (int nt = 0; nt < 8; nt++) {
            const float p0 = __expf(sc[nt][0] - mn0);
            const float p1 = __expf(sc[nt][1] - mn0);
            const float p2 = __expf(sc[nt][2] - mn1);
            const float p3 = __expf(sc[nt][3] - mn1);
            ps0 += p0 + p1;
            ps1 += p2 + p3;
            *reinterpret_cast<float2*>(&Ss[(q0w + g)     * PADS + nt * 8 + tg * 2]) =
                make_float2(f2tff(p0), f2tff(p1));
            *reinterpret_cast<float2*>(&Ss[(q0w + g + 8) * PADS + nt * 8 + tg * 2]) =
                make_float2(f2tff(p2), f2tff(p3));
        }
        ps0 += __shfl_xor_sync(0xffffffffu, ps0, 1);
        ps0 += __shfl_xor_sync(0xffffffffu, ps0, 2);
        ps1 += __shfl_xor_sync(0xffffffffu, ps1, 1);
        ps1 += __shfl_xor_sync(0xffffffffu, ps1, 2);

        lrow0f = lrow0f * corr0 + ps0;
        lrow1f = lrow1f * corr1 + ps1;
        mrow0 = mn0;
        mrow1 = mn1;
#pragma unroll
        for (int nt = 0; nt < 8; nt++) {
            o[nt][0] *= corr0; o[nt][1] *= corr0;
            o[nt][2] *= corr1; o[nt][3] *= corr1;
        }

        __syncwarp();  // Ss rows warp-private

#pragma unroll
        for (int k8 = 0; k8 < 64; k8 += 8) {
            const uint32_t a0 = __float_as_uint(Ss[(q0w + g)     * PADS + k8 + tg]);
            const uint32_t a1 = __float_as_uint(Ss[(q0w + g + 8) * PADS + k8 + tg]);
            const uint32_t a2 = __float_as_uint(Ss[(q0w + g)     * PADS + k8 + tg + 4]);
            const uint32_t a3 = __float_as_uint(Ss[(q0w + g + 8) * PADS + k8 + tg + 4]);
#pragma unroll
            for (int nt = 0; nt < 8; nt++) {
                const uint32_t b0 = __float_as_uint(Vc[(k8 + tg)     * PADV + nt * 8 + g]);
                const uint32_t b1 = __float_as_uint(Vc[(k8 + tg + 4) * PADV + nt * 8 + g]);
                mma_tf32(o[nt], a0, a1, a2, a3, b0, b1);
            }
        }
    }

    const float i0 = 1.0f / lrow0f;
    const float i1 = 1.0f / lrow1f;
    const size_t base0 = (size_t)(b * SEQ + r0) * HID + h * HD;
    const size_t base1 = base0 + (size_t)8 * HID;
#pragma unroll
    for (int nt = 0; nt < 8; nt++) {
        *reinterpret_cast<float2*>(&out[base0 + nt * 8 + tg * 2]) =
            make_float2(f2tff(o[nt][0] * i0), f2tff(o[nt][1] * i0));
        *reinterpret_cast<float2*>(&out[base1 + nt * 8 + tg * 2]) =
            make_float2(f2tff(o[nt][2] * i1), f2tff(o[nt][3] * i1));
    }
}

// ---------------------------------------------------------------------------
extern "C" void kernel_launch(void* const* d_in, const int* in_sizes, int n_in,
                              void* d_out, int out_size)
{
    const float* x     = (const float*)d_in[0];
    const float* W_qkv = (const float*)d_in[1];
    const float* b_qkv = (const float*)d_in[2];
    const float* W_o   = (const float*)d_in[3];
    const float* b_o   = (const float*)d_in[4];
    float* out = (float*)d_out;

    float *qkv, *attn, *xr, *wq, *wo;
    cudaGetSymbolAddress((void**)&qkv,  g_qkv);
    cudaGetSymbolAddress((void**)&attn, g_attn);
    cudaGetSymbolAddress((void**)&xr,   g_x);
    cudaGetSymbolAddress((void**)&wq,   g_wq);
    cudaGetSymbolAddress((void**)&wo,   g_wo);

    const int smem_gemm =
        (GSTG * 128 * GPA + GSTG * BK * GPB) * (int)sizeof(float);   // 75776
    const int smem_attn =
        (64 * PADS + 2 * 64 * PADS + 2 * 64 * PADV) * (int)sizeof(float); // 89088
    cudaFuncSetAttribute(gemm_mma_kernel,
                         cudaFuncAttributeMaxDynamicSharedMemorySize, smem_gemm);
    cudaFuncSetAttribute(attn_mma_kernel,
                         cudaFuncAttributeMaxDynamicSharedMemorySize, smem_attn);

    // 0) pre-round inputs to tf32
    {
        const int n4x = MTOT * HID / 4;
        const int n4q = HID * 3 * HID / 4;
        const int n4o = HID * HID / 4;
        cvt_tf32_kernel<<<(n4x + 255) / 256, 256>>>((const float4*)x,     (float4*)xr, n4x);
        cvt_tf32_kernel<<<(n4q + 255) / 256, 256>>>((const float4*)W_qkv, (float4*)wq, n4q);
        cvt_tf32_kernel<<<(n4o + 255) / 256, 256>>>((const float4*)W_o,   (float4*)wo, n4o);
    }

    // 1) QKV projection (output tf32-rounded)
    gemm_mma_kernel<<<dim3(3 * HID / 128, MTOT / 128), 256, smem_gemm>>>(
        xr, wq, b_qkv, qkv, MTOT, 3 * HID, HID, 1);

    // 2) Causal attention
    attn_mma_kernel<<<dim3(SEQ / 64, NHEAD, BATCH), 128, smem_attn>>>(qkv, attn);

    // 3) Output projection (fp32 output)
    gemm_mma_kernel<<<dim3(HID / 128, MTOT / 128), 256, smem_gemm>>>(
        attn, wo, b_o, out, MTOT, HID, HID, 0);
}